// round 12
// baseline (speedup 1.0000x reference)
#include <cuda_runtime.h>
#include <cuda_bf16.h>
#include <cstdint>

#define NB    64
#define TE    200
#define ENCD  256
#define DECD  1024
#define HATT  128
#define NCONV 32
#define KCONV 31
#define PADC  15
#define PRE   256
#define NC    80
#define TFEAT 1000
#define SSTEPS 500
#define HSZ   (NB*DECD)

#define LOGIT_OFF 5120000
#define ATTW_OFF  5184000

#define GRID  128
#define THR   512

// dynamic smem (bytes): double-buffered W(hi/lo) 128x64 bf16 + act(hi/lo) 64x64 bf16
#define SM_AWH(b)  (1024  + (b)*16384)
#define SM_AWL(b)  (33792 + (b)*16384)
#define SM_BXH(b)  (66560 + (b)*8192)
#define SM_BXL(b)  (82944 + (b)*8192)
#define SM_TOTAL   99328
#define SM_F_OFF   256      // float index of att/outproj scratch (byte 1024)

// ---------------- scratch ----------------
__device__ float g_pm[NB*TE*HATT];
__device__ float g_Wck[HATT*32];
__device__ float g_preH[SSTEPS*NB*PRE];
__device__ float g_P[SSTEPS*NB*PRE];
__device__ __nv_bfloat16 g_Ph[SSTEPS*NB*PRE], g_Pl[SSTEPS*NB*PRE];
__device__ __nv_bfloat16 g_W0h[4096*1536], g_W0l[4096*1536];
__device__ __nv_bfloat16 g_W1h[4096*2048], g_W1l[4096*2048];
__device__ float g_part[4*4096*64];      // [kq][row][batch]
__device__ float g_acf[2*NB*ENCD];
__device__ __nv_bfloat16 g_ach[NB*ENCD], g_acl[NB*ENCD];
__device__ float g_h0f[HSZ], g_c0[HSZ];
__device__ float g_h1f[HSZ], g_c1[HSZ];
__device__ __nv_bfloat16 g_h0h[HSZ], g_h0l[HSZ], g_h1h[HSZ], g_h1l[HSZ];
__device__ float g_acc[NB*TE];
__device__ float g_b40[4096], g_b41[4096];
__device__ unsigned g_flags[GRID];

// ---------------- warp MMA helpers (portable sm_80+, OK on sm_103 non-a) -------
__device__ __forceinline__ uint32_t smem_u32_of(const void* p) {
    uint32_t a;
    asm("{ .reg .u64 t; cvta.to.shared.u64 t, %1; cvt.u32.u64 %0, t; }" : "=r"(a) : "l"(p));
    return a;
}
__device__ __forceinline__ void ldsm4(uint32_t* r, uint32_t addr) {
    asm volatile("ldmatrix.sync.aligned.m8n8.x4.shared.b16 {%0,%1,%2,%3}, [%4];"
        : "=r"(r[0]), "=r"(r[1]), "=r"(r[2]), "=r"(r[3]) : "r"(addr));
}
__device__ __forceinline__ void mma16816(float* c, const uint32_t* a, uint32_t b0, uint32_t b1) {
    asm volatile("mma.sync.aligned.m16n8k16.row.col.f32.bf16.bf16.f32 "
        "{%0,%1,%2,%3}, {%4,%5,%6,%7}, {%8,%9}, {%0,%1,%2,%3};"
        : "+f"(c[0]), "+f"(c[1]), "+f"(c[2]), "+f"(c[3])
        : "r"(a[0]), "r"(a[1]), "r"(a[2]), "r"(a[3]), "r"(b0), "r"(b1));
}

// ---------------- grid barrier: per-block flags + parallel poll ----------------
__device__ __forceinline__ void gbar(unsigned gen) {
    __syncthreads();
    if (threadIdx.x == 0) {
        __threadfence();
        *((volatile unsigned*)&g_flags[blockIdx.x]) = gen;
    }
    if (threadIdx.x < GRID) {
        volatile unsigned* f = g_flags + threadIdx.x;
        while (*f < gen) { __nanosleep(40); }
    }
    __threadfence();
    __syncthreads();
}

// ---------------- merged setup kernel (launch #0) ----------------
__global__ void k_setup(const float* __restrict__ watt, const float* __restrict__ cw,
                        const float* __restrict__ b0a, const float* __restrict__ b0b,
                        const float* __restrict__ b1a, const float* __restrict__ b1b) {
    int i = blockIdx.x * blockDim.x + threadIdx.x;
    if (i < GRID) g_flags[i] = 0u;
    if (i < HSZ) {
        g_h0f[i] = 0.f; g_h1f[i] = 0.f; g_c0[i] = 0.f; g_c1[i] = 0.f;
        __nv_bfloat16 z = __float2bfloat16(0.f);
        g_h0h[i] = z; g_h0l[i] = z; g_h1h[i] = z; g_h1l[i] = z;
    }
    if (i < 4096) { g_b40[i] = b0a[i] + b0b[i]; g_b41[i] = b1a[i] + b1b[i]; }
    if (i < HATT * 32) {
        int h = i >> 5, k = i & 31;
        float s = 0.f;
        if (k < KCONV) {
            #pragma unroll
            for (int c = 0; c < NCONV; c++) s += watt[h * NCONV + c] * cw[c * KCONV + k];
        }
        g_Wck[i] = s;
    }
}

// ---------------- merged conversion kernel (launch #4) ----------------
#define N_W0 (4096*1536)
#define N_W1 (4096*2048)
#define N_P  (SSTEPS*NB*PRE)
__global__ void k_cvtAll(const float* __restrict__ l0wih, const float* __restrict__ l0whh,
                         const float* __restrict__ l1wih, const float* __restrict__ l1whh) {
    int idx = blockIdx.x * blockDim.x + threadIdx.x;
    if (idx < N_W0) {
        int r = idx / 1536, k = idx - r * 1536;
        float v = (k < 512) ? l0wih[(size_t)r * 512 + k] : l0whh[(size_t)r * 1024 + (k - 512)];
        __nv_bfloat16 hi = __float2bfloat16(v);
        g_W0h[idx] = hi;
        g_W0l[idx] = __float2bfloat16(v - __bfloat162float(hi));
    } else if (idx < N_W0 + N_W1) {
        int j = idx - N_W0;
        int r = j / 2048, k = j - r * 2048;
        float v = (k < 1024) ? l1wih[(size_t)r * 1024 + k] : l1whh[(size_t)r * 1024 + (k - 1024)];
        __nv_bfloat16 hi = __float2bfloat16(v);
        g_W1h[j] = hi;
        g_W1l[j] = __float2bfloat16(v - __bfloat162float(hi));
    } else if (idx < N_W0 + N_W1 + N_P) {
        int j = idx - N_W0 - N_W1;
        float v = g_P[j];
        __nv_bfloat16 hi = __float2bfloat16(v);
        g_Ph[j] = hi;
        g_Pl[j] = __float2bfloat16(v - __bfloat162float(hi));
    }
}

// ---------------- setup GEMM (validated):  C = A*W^T (+bias, relu) -------------
template<int LOADER>
__global__ __launch_bounds__(256) void k_gemm(
    const float* __restrict__ A, const float* __restrict__ W,
    const float* __restrict__ bias, float* __restrict__ Cout,
    int N, int K, int lda, const float* __restrict__ ft, int relu)
{
    __shared__ float As[16][68];
    __shared__ float Ws[16][68];
    int tid  = threadIdx.x;
    int mb = blockIdx.x * 64, nb = blockIdx.y * 64;
    int la_m = tid >> 2, la_k = (tid & 3) << 2;
    int tx = tid & 15, ty = tid >> 4;
    float acc[4][4] = {};

    for (int k0 = 0; k0 < K; k0 += 16) {
        float4 av;
        if (LOADER == 0) {
            av = *reinterpret_cast<const float4*>(A + (size_t)(mb + la_m) * lda + k0 + la_k);
        } else {
            int row = mb + la_m;
            int s = row >> 6, bb = row & 63;
            float t0 = 0.f, t1 = 0.f, t2 = 0.f, t3 = 0.f;
            if (s > 0) {
                int base = (s - 1) * 2;
                int k = k0 + la_k;
                const float* fb = ft + (size_t)bb * NC * TFEAT;
                t0 = fb[(k % NC) * TFEAT + base + k / NC]; k++;
                t1 = fb[(k % NC) * TFEAT + base + k / NC]; k++;
                t2 = fb[(k % NC) * TFEAT + base + k / NC]; k++;
                t3 = fb[(k % NC) * TFEAT + base + k / NC];
            }
            av = make_float4(t0, t1, t2, t3);
        }
        As[la_k][la_m] = av.x; As[la_k+1][la_m] = av.y;
        As[la_k+2][la_m] = av.z; As[la_k+3][la_m] = av.w;
        float4 wv = *reinterpret_cast<const float4*>(W + (size_t)(nb + la_m) * K + k0 + la_k);
        Ws[la_k][la_m] = wv.x; Ws[la_k+1][la_m] = wv.y;
        Ws[la_k+2][la_m] = wv.z; Ws[la_k+3][la_m] = wv.w;
        __syncthreads();
        #pragma unroll
        for (int k = 0; k < 16; k++) {
            float4 a = *reinterpret_cast<const float4*>(&As[k][ty << 2]);
            float4 b = *reinterpret_cast<const float4*>(&Ws[k][tx << 2]);
            acc[0][0] += a.x*b.x; acc[0][1] += a.x*b.y; acc[0][2] += a.x*b.z; acc[0][3] += a.x*b.w;
            acc[1][0] += a.y*b.x; acc[1][1] += a.y*b.y; acc[1][2] += a.y*b.z; acc[1][3] += a.y*b.w;
            acc[2][0] += a.z*b.x; acc[2][1] += a.z*b.y; acc[2][2] += a.z*b.z; acc[2][3] += a.z*b.w;
            acc[3][0] += a.w*b.x; acc[3][1] += a.w*b.y; acc[3][2] += a.w*b.z; acc[3][3] += a.w*b.w;
        }
        __syncthreads();
    }
    #pragma unroll
    for (int i = 0; i < 4; i++) {
        int m = mb + (ty << 2) + i;
        #pragma unroll
        for (int j = 0; j < 4; j++) {
            int n = nb + (tx << 2) + j;
            float v = acc[i][j] + bias[n];
            if (relu) v = fmaxf(v, 0.f);
            Cout[(size_t)m * N + n] = v;
        }
    }
}

// ---------------- GEMM-phase chunk load/store (validated layout) ----------------
struct Regs6 { uint4 v[6]; };

__device__ __forceinline__ void ldg_chunk(Regs6& R,
    const __nv_bfloat16* __restrict__ Wh, const __nv_bfloat16* __restrict__ Wl,
    const __nv_bfloat16* __restrict__ Bh, const __nv_bfloat16* __restrict__ Bl,
    int bstr, int KT, int rowbase, int k0, int koff, int tid)
{
    #pragma unroll
    for (int j = 0; j < 2; j++) {
        int seg = tid + j * 512;
        int r = seg >> 3, cs = seg & 7;
        size_t off = (size_t)(rowbase + r) * KT + k0 + cs * 8;
        R.v[j]     = *reinterpret_cast<const uint4*>(Wh + off);
        R.v[2 + j] = *reinterpret_cast<const uint4*>(Wl + off);
    }
    {
        int r = tid >> 3, cs = tid & 7;
        size_t off = (size_t)r * bstr + koff + cs * 8;
        R.v[4] = *reinterpret_cast<const uint4*>(Bh + off);
        R.v[5] = *reinterpret_cast<const uint4*>(Bl + off);
    }
}

__device__ __forceinline__ void sts_chunk(const Regs6& R, char* sm, int buf, int tid) {
    #pragma unroll
    for (int j = 0; j < 2; j++) {
        int seg = tid + j * 512;
        int r = seg >> 3, cs = seg & 7;
        uint32_t off = r * 128 + cs * 16;
        uint32_t sw = off ^ ((off >> 3) & 0x70);
        *reinterpret_cast<uint4*>(sm + SM_AWH(buf) + sw) = R.v[j];
        *reinterpret_cast<uint4*>(sm + SM_AWL(buf) + sw) = R.v[2 + j];
    }
    {
        int r = tid >> 3, cs = tid & 7;
        uint32_t off = r * 128 + cs * 16;
        uint32_t sw = off ^ ((off >> 3) & 0x70);
        *reinterpret_cast<uint4*>(sm + SM_BXH(buf) + sw) = R.v[4];
        *reinterpret_cast<uint4*>(sm + SM_BXL(buf) + sw) = R.v[5];
    }
}

// ---------------- one LSTM GEMM phase via mma.sync (bf16 3-term split) ---------
template<int L>
__device__ void gemm_phase(char* sm, uint32_t smb, int rb, int kq, int s,
    const __nv_bfloat16* __restrict__ Wh, const __nv_bfloat16* __restrict__ Wl,
    int tid)
{
    constexpr int KT = L ? 2048 : 1536;
    constexpr int NCH = L ? 8 : 6;
    const int rowbase = rb * 128;
    const int kqbase = kq * (KT / 4);

    const int warp = tid >> 5, lane = tid & 31;
    const int mt = warp >> 1;            // 0..7
    const int nh = (warp & 1) * 32;      // 0 or 32

    const int ar = mt * 16 + (lane & 15);
    const uint32_t aoff0 = (uint32_t)ar * 128 + (uint32_t)(lane >> 4) * 16;
    const uint32_t amx = (uint32_t)(ar & 7) << 4;
    const int bn0 = nh + ((lane >> 4) & 1) * 8 + (lane & 7);
    const uint32_t boff0 = (uint32_t)bn0 * 128 + (uint32_t)((lane >> 3) & 1) * 16;
    const uint32_t bmx = (uint32_t)(bn0 & 7) << 4;

    auto resolveB = [&](int k0, const __nv_bfloat16*& bh, const __nv_bfloat16*& bl,
                        int& bstr, int& koff) {
        if (L == 0) {
            if (k0 < 256)      { bh = g_ach; bl = g_acl; bstr = 256; koff = k0; }
            else if (k0 < 512) { bh = g_Ph + (size_t)s * NB * PRE;
                                 bl = g_Pl + (size_t)s * NB * PRE; bstr = 256; koff = k0 - 256; }
            else               { bh = g_h0h; bl = g_h0l; bstr = 1024; koff = k0 - 512; }
        } else {
            bstr = 1024;
            if (k0 < 1024) { bh = g_h0h; bl = g_h0l; koff = k0; }
            else           { bh = g_h1h; bl = g_h1l; koff = k0 - 1024; }
        }
    };

    float acc[4][4];
    #pragma unroll
    for (int nt = 0; nt < 4; nt++)
        #pragma unroll
        for (int q = 0; q < 4; q++) acc[nt][q] = 0.f;

    {   // prologue: chunk 0 -> buf 0
        Regs6 R; const __nv_bfloat16 *bh, *bl; int bstr, koff;
        resolveB(kqbase, bh, bl, bstr, koff);
        ldg_chunk(R, Wh, Wl, bh, bl, bstr, KT, rowbase, kqbase, koff, tid);
        sts_chunk(R, sm, 0, tid);
    }
    __syncthreads();

    for (int i = 0; i < NCH; i++) {
        Regs6 R;
        const int buf = i & 1;
        const bool more = (i + 1 < NCH);
        if (more) {
            int k0 = kqbase + (i + 1) * 64;
            const __nv_bfloat16 *bh, *bl; int bstr, koff;
            resolveB(k0, bh, bl, bstr, koff);
            ldg_chunk(R, Wh, Wl, bh, bl, bstr, KT, rowbase, k0, koff, tid);
        }
        const uint32_t awh = smb + SM_AWH(buf), awl = smb + SM_AWL(buf);
        const uint32_t bxh = smb + SM_BXH(buf), bxl = smb + SM_BXL(buf);
        #pragma unroll
        for (int kk = 0; kk < 4; kk++) {
            const uint32_t col = kk * 32;
            uint32_t ah[4], al[4], bh0[4], bh1[4], bl0[4], bl1[4];
            const uint32_t aof = (aoff0 + col) ^ amx;
            ldsm4(ah, awh + aof);
            ldsm4(al, awl + aof);
            const uint32_t bof = (boff0 + col) ^ bmx;
            ldsm4(bh0, bxh + bof);
            ldsm4(bh1, bxh + bof + 2048);
            ldsm4(bl0, bxl + bof);
            ldsm4(bl1, bxl + bof + 2048);
            mma16816(acc[0], ah, bh0[0], bh0[1]);
            mma16816(acc[1], ah, bh0[2], bh0[3]);
            mma16816(acc[2], ah, bh1[0], bh1[1]);
            mma16816(acc[3], ah, bh1[2], bh1[3]);
            mma16816(acc[0], ah, bl0[0], bl0[1]);
            mma16816(acc[1], ah, bl0[2], bl0[3]);
            mma16816(acc[2], ah, bl1[0], bl1[1]);
            mma16816(acc[3], ah, bl1[2], bl1[3]);
            mma16816(acc[0], al, bh0[0], bh0[1]);
            mma16816(acc[1], al, bh0[2], bh0[3]);
            mma16816(acc[2], al, bh1[0], bh1[1]);
            mma16816(acc[3], al, bh1[2], bh1[3]);
        }
        if (more) sts_chunk(R, sm, buf ^ 1, tid);
        __syncthreads();
    }

    // epilogue: write fp32 partials
    {
        const int trow = lane >> 2, tcol = (lane & 3) * 2;
        #pragma unroll
        for (int nt = 0; nt < 4; nt++) {
            int row = rowbase + mt * 16 + trow;
            int col = nh + nt * 8 + tcol;
            float* dst = g_part + ((size_t)kq * 4096 + row) * 64 + col;
            *reinterpret_cast<float2*>(dst) = make_float2(acc[nt][0], acc[nt][1]);
            *reinterpret_cast<float2*>(dst + 8 * 64) = make_float2(acc[nt][2], acc[nt][3]);
        }
    }
}

// ---------------- pointwise + zoneout + bf16 split ----------------
__device__ void pw_phase(int u0, const float* __restrict__ b4,
    float* __restrict__ hf, __nv_bfloat16* __restrict__ hh, __nv_bfloat16* __restrict__ hl,
    float* __restrict__ cf, int tid)
{
    int ul = tid >> 6, bat = tid & 63;
    int u = u0 + ul;
    float g[4];
    #pragma unroll
    for (int gg = 0; gg < 4; gg++) {
        int row = gg * 1024 + u;
        float v = b4[row];
        #pragma unroll
        for (int kq = 0; kq < 4; kq++)
            v += g_part[((size_t)kq * 4096 + row) * 64 + bat];
        g[gg] = v;
    }
    int idx = bat * 1024 + u;
    float cold = cf[idx], hold = hf[idx];
    float si = 1.f / (1.f + __expf(-g[0]));
    float sf = 1.f / (1.f + __expf(-g[1]));
    float so = 1.f / (1.f + __expf(-g[3]));
    float c2 = sf * cold + si * tanhf(g[2]);
    float h2 = so * tanhf(c2);
    float hn = 0.1f * hold + 0.9f * h2;
    float cn = 0.1f * cold + 0.9f * c2;
    hf[idx] = hn; cf[idx] = cn;
    __nv_bfloat16 hi = __float2bfloat16(hn);
    hh[idx] = hi;
    hl[idx] = __float2bfloat16(hn - __bfloat162float(hi));
}

// ---------------- attention (512-thread; validated math) ----------------
__device__ void att_step(float* __restrict__ smf, int s, int b,
    const float* __restrict__ enc, const int* __restrict__ text_len,
    const float* __restrict__ wdec, const float* __restrict__ watt,
    const float* __restrict__ watt_b, float* __restrict__ attw_out)
{
    float* sWck = smf;                  // 4224
    float* apad = smf + 4224;           // 232
    float* dp   = smf + 4456;           // 128
    float* w_s  = smf + 4584;           // 128
    float* sE   = smf + 4712;           // 200
    float* red  = smf + 4912;           // 48
    float* hrow = smf + 4960;           // 1024 (h0 row staged in smem)
    float* ctx  = smf + 5984;           // 512 (context partials)
    int tid = threadIdx.x, lane = tid & 31, wid = tid >> 5;
    int len = text_len[b];

    for (int i = tid; i < HATT * 33; i += THR) {
        int h = i / 33, k = i - h * 33;
        sWck[i] = (k < 31) ? g_Wck[h * 32 + k] : 0.f;
    }
    if (tid < 16)  apad[tid] = 0.f;
    if (tid < 17)  apad[215 + tid] = 0.f;
    if (tid < 200) {
        float v = (s == 0) ? ((tid < len) ? 1.f / (float)len : 0.f) : g_acc[b * TE + tid];
        apad[PADC + tid] = v;
    }
    if (tid < HATT) w_s[tid] = watt[tid];
    if (tid < DECD / 4)
        reinterpret_cast<float4*>(hrow)[tid] =
            reinterpret_cast<const float4*>(g_h0f + b * DECD)[tid];
    __syncthreads();

    {
        const float4* hr4 = reinterpret_cast<const float4*>(hrow);
        for (int h = wid; h < HATT; h += 16) {
            const float4* wr = reinterpret_cast<const float4*>(wdec + (size_t)h * DECD);
            float p = 0.f;
            #pragma unroll
            for (int j = lane; j < 256; j += 32) {
                float4 w = wr[j]; float4 hv = hr4[j];
                p += w.x*hv.x + w.y*hv.y + w.z*hv.z + w.w*hv.w;
            }
            #pragma unroll
            for (int o = 16; o; o >>= 1) p += __shfl_xor_sync(0xffffffffu, p, o);
            if (lane == 0) dp[h] = p;
        }
    }
    __syncthreads();

    const float wb0 = watt_b[0];
    for (int it = 0; it < 13; it++) {
        int t = it * 16 + wid;
        if (t < TE) {
            const float* pmrow = g_pm + ((size_t)(b * TE + t)) * HATT;
            float esum = 0.f;
            #pragma unroll
            for (int hh = 0; hh < 4; hh++) {
                int h = lane + (hh << 5);
                const float* wc = sWck + h * 33;
                float conv = 0.f;
                #pragma unroll
                for (int k = 0; k < 31; k++) conv += wc[k] * apad[t + k];
                float x = conv + dp[h] + pmrow[h];
                float ez = __expf(2.f * x);
                float th = 1.f - __fdividef(2.f, ez + 1.f);
                esum += w_s[h] * th;
            }
            #pragma unroll
            for (int o = 16; o; o >>= 1) esum += __shfl_xor_sync(0xffffffffu, esum, o);
            if (lane == 0) sE[t] = esum + wb0;
        }
    }
    __syncthreads();

    float e = (tid < len) ? sE[tid] : -1e30f;
    float mx = e;
    #pragma unroll
    for (int o = 16; o; o >>= 1) mx = fmaxf(mx, __shfl_xor_sync(0xffffffffu, mx, o));
    if (lane == 0) red[wid] = mx;
    __syncthreads();
    if (tid == 0) {
        float mm = red[0];
        for (int i = 1; i < 16; i++) mm = fmaxf(mm, red[i]);
        red[16] = mm;
    }
    __syncthreads();
    mx = red[16];
    float ex = (tid < 200) ? __expf(e - mx) : 0.f;
    float sm = ex;
    #pragma unroll
    for (int o = 16; o; o >>= 1) sm += __shfl_xor_sync(0xffffffffu, sm, o);
    if (lane == 0) red[wid] = sm;
    __syncthreads();
    if (tid == 0) {
        float ss = 0.f;
        for (int i = 0; i < 16; i++) ss += red[i];
        red[17] = ss;
    }
    __syncthreads();
    float inv = 1.f / red[17];
    __syncthreads();
    if (tid < 200) {
        float aw = ex * inv;
        sE[tid] = aw;
        attw_out[((size_t)b * SSTEPS + s) * TE + tid] = aw;
        float an = (s == 0) ? aw : g_acc[b * TE + tid] + aw;
        g_acc[b * TE + tid] = an;
    }
    __syncthreads();

    // context: 512 threads, 2 t-halves x 256 channels (halves the L2 chain)
    {
        int th = tid >> 8, c = tid & 255;
        const float* er = enc + ((size_t)b * TE + th * 100) * ENCD + c;
        float a0 = 0.f, a1 = 0.f, a2 = 0.f, a3 = 0.f;
        const float* se = sE + th * 100;
        #pragma unroll 5
        for (int t = 0; t < 100; t += 4) {
            a0 += se[t]     * er[(size_t)t * ENCD];
            a1 += se[t + 1] * er[(size_t)(t + 1) * ENCD];
            a2 += se[t + 2] * er[(size_t)(t + 2) * ENCD];
            a3 += se[t + 3] * er[(size_t)(t + 3) * ENCD];
        }
        ctx[th * 256 + c] = (a0 + a1) + (a2 + a3);
    }
    __syncthreads();
    if (tid < ENCD) {
        float ac = ctx[tid] + ctx[256 + tid];
        g_acf[(size_t)(s & 1) * NB * ENCD + b * ENCD + tid] = ac;
        __nv_bfloat16 hi = __float2bfloat16(ac);
        g_ach[b * ENCD + tid] = hi;
        g_acl[b * ENCD + tid] = __float2bfloat16(ac - __bfloat162float(hi));
    }
    __syncthreads();
}

// ---------------- output projection: 4 batch-tiles x 16 row-tiles over 64 blocks -
__device__ void outproj(float* __restrict__ smf, int s, int j,
    const float* __restrict__ fw, const float* __restrict__ pwm,
    const float* __restrict__ pb, float* __restrict__ out)
{
    int tid = threadIdx.x, lane = tid & 31, wid = tid >> 5;
    int bt = j >> 4;            // batch tile (16 batches)
    int ot = j & 15;            // o-row stride class
    const float* acb = g_acf + (size_t)(s & 1) * NB * ENCD;
    float* hcs = smf;           // 16 * 1280 floats = 80 KB

    // stage 16 hcs vectors
    for (int i = tid; i < 16 * 320; i += THR) {
        int bb = i / 320, ii = i - bb * 320;
        int b = bt * 16 + bb;
        float4 v;
        if (ii < 256) v = reinterpret_cast<const float4*>(g_h1f + (size_t)b * DECD)[ii];
        else          v = reinterpret_cast<const float4*>(acb + (size_t)b * ENCD)[ii - 256];
        reinterpret_cast<float4*>(hcs + bb * 1280)[ii] = v;
    }
    __syncthreads();

    int nrows = (162 - ot + 15) >> 4;
    for (int task = wid; task < nrows * 2; task += 16) {
        int r = ot + (task >> 1) * 16;
        int bh = (task & 1) * 8;
        const float* row = (r < 160) ? (fw + (size_t)r * 1280) : (pwm + (size_t)(r - 160) * 1280);
        const float4* r4 = reinterpret_cast<const float4*>(row);
        float4 w[10];
        #pragma unroll
        for (int q = 0; q < 10; q++) w[q] = r4[lane + q * 32];
        #pragma unroll
        for (int bb = 0; bb < 8; bb++) {
            const float4* h4 = reinterpret_cast<const float4*>(hcs + (size_t)(bh + bb) * 1280);
            float sum = 0.f;
            #pragma unroll
            for (int q = 0; q < 10; q++) {
                float4 hv = h4[lane + q * 32];
                sum += w[q].x*hv.x + w[q].y*hv.y + w[q].z*hv.z + w[q].w*hv.w;
            }
            #pragma unroll
            for (int of = 16; of; of >>= 1) sum += __shfl_xor_sync(0xffffffffu, sum, of);
            if (lane == 0) {
                int b = bt * 16 + bh + bb;
                if (r < 160) {
                    int rr = r / NC, ch = r - rr * NC;
                    out[(size_t)b * NC * TFEAT + (size_t)ch * TFEAT + s * 2 + rr] = sum;
                } else {
                    out[LOGIT_OFF + (size_t)b * TFEAT + s * 2 + (r - 160)] = sum + pb[r - 160];
                }
            }
        }
    }
    __syncthreads();
}

// ---------------- persistent decoder ----------------
__global__ void __launch_bounds__(THR, 1) k_decoder(
    const float* __restrict__ enc, const int* __restrict__ tlen,
    const float* __restrict__ wdec, const float* __restrict__ watt,
    const float* __restrict__ wattb,
    const float* __restrict__ fow, const float* __restrict__ pow_,
    const float* __restrict__ pob, float* __restrict__ out)
{
    extern __shared__ char sm[];
    float* smf = reinterpret_cast<float*>(sm) + SM_F_OFF;
    uint32_t smb = smem_u32_of(sm);
    int tid = threadIdx.x;
    int blk = blockIdx.x;
    int rb = blk >> 2, kq = blk & 3;
    float* attw = out + ATTW_OFF;
    unsigned gen = 0;

    // phase 0: attention for step 0 (h0 = 0, uniform prior)
    if (blk < 64)
        att_step(smf, 0, blk, enc, tlen, wdec, watt, wattb, attw);
    gen++; gbar(gen);

    for (int s = 0; s < SSTEPS; s++) {
        // A: lstm0 GEMM
        gemm_phase<0>(sm, smb, rb, kq, s, g_W0h, g_W0l, tid);
        gen++; gbar(gen);
        // B: pw0 (all) + outproj(s-1) on blocks >= 64
        pw_phase(blk * 8, g_b40, g_h0f, g_h0h, g_h0l, g_c0, tid);
        if (blk >= 64 && s >= 1)
            outproj(smf, s - 1, blk - 64, fow, pow_, pob, out);
        gen++; gbar(gen);
        // C: lstm1 GEMM
        gemm_phase<1>(sm, smb, rb, kq, s, g_W1h, g_W1l, tid);
        gen++; gbar(gen);
        // D: pw1 (all) + attention(s+1) on blocks < 64
        pw_phase(blk * 8, g_b41, g_h1f, g_h1h, g_h1l, g_c1, tid);
        if (blk < 64 && s + 1 < SSTEPS)
            att_step(smf, s + 1, blk, enc, tlen, wdec, watt, wattb, attw);
        gen++; gbar(gen);
    }
    // tail: outproj for the last step
    if (blk >= 64)
        outproj(smf, SSTEPS - 1, blk - 64, fow, pow_, pob, out);
}

// ---------------- host ----------------
static float* symaddr(const void* sym) {
    void* p = nullptr;
    cudaGetSymbolAddress(&p, sym);
    return (float*)p;
}

extern "C" void kernel_launch(void* const* d_in, const int* in_sizes, int n_in,
                              void* d_out, int out_size)
{
    const float* enc    = (const float*)d_in[0];
    const int*   tlen   = (const int*)  d_in[1];
    const float* ft     = (const float*)d_in[2];
    const float* enc_w  = (const float*)d_in[3];
    const float* enc_b  = (const float*)d_in[4];
    const float* dec_w  = (const float*)d_in[5];
    const float* att_w  = (const float*)d_in[6];
    const float* conv_w = (const float*)d_in[7];
    const float* ww     = (const float*)d_in[8];
    const float* wbb    = (const float*)d_in[9];
    const float* pw0    = (const float*)d_in[10];
    const float* pb0    = (const float*)d_in[11];
    const float* pw1    = (const float*)d_in[12];
    const float* pb1    = (const float*)d_in[13];
    const float* l0wih  = (const float*)d_in[14];
    const float* l0whh  = (const float*)d_in[15];
    const float* l0bih  = (const float*)d_in[16];
    const float* l0bhh  = (const float*)d_in[17];
    const float* l1wih  = (const float*)d_in[18];
    const float* l1whh  = (const float*)d_in[19];
    const float* l1bih  = (const float*)d_in[20];
    const float* l1bhh  = (const float*)d_in[21];
    const float* fow    = (const float*)d_in[22];
    const float* pow_   = (const float*)d_in[23];
    const float* pob    = (const float*)d_in[24];
    float* out = (float*)d_out;

    float* pm_p = symaddr(g_pm);
    float* preH = symaddr(g_preH);
    float* Pp   = symaddr(g_P);

    static int smem_set = 0;
    if (!smem_set) {
        cudaFuncSetAttribute(k_decoder, cudaFuncAttributeMaxDynamicSharedMemorySize, SM_TOTAL);
        smem_set = 1;
    }

    // launches 0..4 are setup; k_decoder is launch index 5 (ncu -s 5 -c 1 captures it)
    k_setup<<<(HSZ + 255) / 256, 256>>>(att_w, conv_w, l0bih, l0bhh, l1bih, l1bhh);
    k_gemm<0><<<dim3(200, 2), 256>>>(enc, enc_w, enc_b, pm_p, 128, 256, 256, nullptr, 0);
    k_gemm<1><<<dim3(500, 4), 256>>>(nullptr, pw0, pb0, preH, 256, 160, 0, ft, 1);
    k_gemm<0><<<dim3(500, 4), 256>>>(preH, pw1, pb1, Pp, 256, 256, 256, nullptr, 1);
    k_cvtAll<<<(N_W0 + N_W1 + N_P + 255) / 256, 256>>>(l0wih, l0whh, l1wih, l1whh);

    k_decoder<<<GRID, THR, SM_TOTAL>>>(
        enc, tlen, dec_w, ww, wbb, fow, pow_, pob, out);
}

// round 13
// speedup vs baseline: 1.1621x; 1.1621x over previous
#include <cuda_runtime.h>
#include <cuda_bf16.h>
#include <cstdint>

#define NB    64
#define TE    200
#define ENCD  256
#define DECD  1024
#define HATT  128
#define NCONV 32
#define KCONV 31
#define PADC  15
#define PRE   256
#define NC    80
#define TFEAT 1000
#define SSTEPS 500
#define HSZ   (NB*DECD)

#define LOGIT_OFF 5120000
#define ATTW_OFF  5184000

#define GRID  128
#define THR   512

// dynamic smem (bytes): double-buffered W(hi/lo) 128x64 bf16 + act(hi/lo) 64x64 bf16
#define SM_AWH(b)  (1024  + (b)*16384)
#define SM_AWL(b)  (33792 + (b)*16384)
#define SM_BXH(b)  (66560 + (b)*8192)
#define SM_BXL(b)  (82944 + (b)*8192)
#define SM_TOTAL   99328
#define SM_F_OFF   256      // float index of att/outproj scratch (byte 1024)

// att conv-MMA smem layout (bytes from sm base; reuses GEMM buffer space in phase D)
#define SM_CA_H   8192      // Wck hi: 128 rows x 80 B
#define SM_CA_L   18432     // Wck lo
#define SM_CB_H   28672     // im2col apad hi: 208 rows x 80 B
#define SM_CB_L   45312     // im2col apad lo

// ---------------- scratch ----------------
__device__ float g_pm[NB*TE*HATT];
__device__ float g_pmT[NB*HATT*TE];     // [b][h][t]
__device__ float g_Wck[HATT*32];
__device__ __nv_bfloat16 g_Wckh[HATT*32], g_Wckl[HATT*32];
__device__ float g_preH[SSTEPS*NB*PRE];
__device__ float g_P[SSTEPS*NB*PRE];
__device__ __nv_bfloat16 g_Ph[SSTEPS*NB*PRE], g_Pl[SSTEPS*NB*PRE];
__device__ __nv_bfloat16 g_W0h[4096*1536], g_W0l[4096*1536];
__device__ __nv_bfloat16 g_W1h[4096*2048], g_W1l[4096*2048];
__device__ float g_part[4*4096*64];      // [kq][row][batch]
__device__ float g_acf[2*NB*ENCD];
__device__ __nv_bfloat16 g_ach[NB*ENCD], g_acl[NB*ENCD];
__device__ float g_h0f[HSZ], g_c0[HSZ];
__device__ float g_h1f[HSZ], g_c1[HSZ];
__device__ __nv_bfloat16 g_h0h[HSZ], g_h0l[HSZ], g_h1h[HSZ], g_h1l[HSZ];
__device__ float g_acc[NB*TE];
__device__ float g_b40[4096], g_b41[4096];
__device__ unsigned g_flags[GRID];

// ---------------- warp MMA helpers (portable sm_80+, OK on sm_103 non-a) -------
__device__ __forceinline__ uint32_t smem_u32_of(const void* p) {
    uint32_t a;
    asm("{ .reg .u64 t; cvta.to.shared.u64 t, %1; cvt.u32.u64 %0, t; }" : "=r"(a) : "l"(p));
    return a;
}
__device__ __forceinline__ void ldsm4(uint32_t* r, uint32_t addr) {
    asm volatile("ldmatrix.sync.aligned.m8n8.x4.shared.b16 {%0,%1,%2,%3}, [%4];"
        : "=r"(r[0]), "=r"(r[1]), "=r"(r[2]), "=r"(r[3]) : "r"(addr));
}
__device__ __forceinline__ void mma16816(float* c, const uint32_t* a, uint32_t b0, uint32_t b1) {
    asm volatile("mma.sync.aligned.m16n8k16.row.col.f32.bf16.bf16.f32 "
        "{%0,%1,%2,%3}, {%4,%5,%6,%7}, {%8,%9}, {%0,%1,%2,%3};"
        : "+f"(c[0]), "+f"(c[1]), "+f"(c[2]), "+f"(c[3])
        : "r"(a[0]), "r"(a[1]), "r"(a[2]), "r"(a[3]), "r"(b0), "r"(b1));
}

// ---------------- grid barrier: per-block flags + parallel poll ----------------
__device__ __forceinline__ void gbar(unsigned gen) {
    __syncthreads();
    if (threadIdx.x == 0) {
        __threadfence();
        *((volatile unsigned*)&g_flags[blockIdx.x]) = gen;
    }
    if (threadIdx.x < GRID) {
        volatile unsigned* f = g_flags + threadIdx.x;
        while (*f < gen) { __nanosleep(40); }
    }
    __threadfence();
    __syncthreads();
}

// ---------------- merged setup kernel (launch #0) ----------------
__global__ void k_setup(const float* __restrict__ watt, const float* __restrict__ cw,
                        const float* __restrict__ b0a, const float* __restrict__ b0b,
                        const float* __restrict__ b1a, const float* __restrict__ b1b) {
    int i = blockIdx.x * blockDim.x + threadIdx.x;
    if (i < GRID) g_flags[i] = 0u;
    if (i < HSZ) {
        g_h0f[i] = 0.f; g_h1f[i] = 0.f; g_c0[i] = 0.f; g_c1[i] = 0.f;
        __nv_bfloat16 z = __float2bfloat16(0.f);
        g_h0h[i] = z; g_h0l[i] = z; g_h1h[i] = z; g_h1l[i] = z;
    }
    if (i < 4096) { g_b40[i] = b0a[i] + b0b[i]; g_b41[i] = b1a[i] + b1b[i]; }
    if (i < HATT * 32) {
        int h = i >> 5, k = i & 31;
        float s = 0.f;
        if (k < KCONV) {
            #pragma unroll
            for (int c = 0; c < NCONV; c++) s += watt[h * NCONV + c] * cw[c * KCONV + k];
        }
        g_Wck[i] = s;
        __nv_bfloat16 hi = __float2bfloat16(s);
        g_Wckh[i] = hi;
        g_Wckl[i] = __float2bfloat16(s - __bfloat162float(hi));
    }
}

// ---------------- merged conversion kernel (launch #4) ----------------
#define N_W0 (4096*1536)
#define N_W1 (4096*2048)
#define N_P  (SSTEPS*NB*PRE)
#define N_PM (NB*TE*HATT)
__global__ void k_cvtAll(const float* __restrict__ l0wih, const float* __restrict__ l0whh,
                         const float* __restrict__ l1wih, const float* __restrict__ l1whh) {
    int idx = blockIdx.x * blockDim.x + threadIdx.x;
    if (idx < N_W0) {
        int r = idx / 1536, k = idx - r * 1536;
        float v = (k < 512) ? l0wih[(size_t)r * 512 + k] : l0whh[(size_t)r * 1024 + (k - 512)];
        __nv_bfloat16 hi = __float2bfloat16(v);
        g_W0h[idx] = hi;
        g_W0l[idx] = __float2bfloat16(v - __bfloat162float(hi));
    } else if (idx < N_W0 + N_W1) {
        int j = idx - N_W0;
        int r = j / 2048, k = j - r * 2048;
        float v = (k < 1024) ? l1wih[(size_t)r * 1024 + k] : l1whh[(size_t)r * 1024 + (k - 1024)];
        __nv_bfloat16 hi = __float2bfloat16(v);
        g_W1h[j] = hi;
        g_W1l[j] = __float2bfloat16(v - __bfloat162float(hi));
    } else if (idx < N_W0 + N_W1 + N_P) {
        int j = idx - N_W0 - N_W1;
        float v = g_P[j];
        __nv_bfloat16 hi = __float2bfloat16(v);
        g_Ph[j] = hi;
        g_Pl[j] = __float2bfloat16(v - __bfloat162float(hi));
    } else if (idx < N_W0 + N_W1 + N_P + N_PM) {
        int j = idx - N_W0 - N_W1 - N_P;   // j = (b*TE + t)*HATT + h
        int h = j & (HATT - 1);
        int bt = j >> 7;
        int t = bt % TE, b = bt / TE;
        g_pmT[((size_t)b * HATT + h) * TE + t] = g_pm[j];
    }
}

// ---------------- setup GEMM (validated):  C = A*W^T (+bias, relu) -------------
template<int LOADER>
__global__ __launch_bounds__(256) void k_gemm(
    const float* __restrict__ A, const float* __restrict__ W,
    const float* __restrict__ bias, float* __restrict__ Cout,
    int N, int K, int lda, const float* __restrict__ ft, int relu)
{
    __shared__ float As[16][68];
    __shared__ float Ws[16][68];
    int tid  = threadIdx.x;
    int mb = blockIdx.x * 64, nb = blockIdx.y * 64;
    int la_m = tid >> 2, la_k = (tid & 3) << 2;
    int tx = tid & 15, ty = tid >> 4;
    float acc[4][4] = {};

    for (int k0 = 0; k0 < K; k0 += 16) {
        float4 av;
        if (LOADER == 0) {
            av = *reinterpret_cast<const float4*>(A + (size_t)(mb + la_m) * lda + k0 + la_k);
        } else {
            int row = mb + la_m;
            int s = row >> 6, bb = row & 63;
            float t0 = 0.f, t1 = 0.f, t2 = 0.f, t3 = 0.f;
            if (s > 0) {
                int base = (s - 1) * 2;
                int k = k0 + la_k;
                const float* fb = ft + (size_t)bb * NC * TFEAT;
                t0 = fb[(k % NC) * TFEAT + base + k / NC]; k++;
                t1 = fb[(k % NC) * TFEAT + base + k / NC]; k++;
                t2 = fb[(k % NC) * TFEAT + base + k / NC]; k++;
                t3 = fb[(k % NC) * TFEAT + base + k / NC];
            }
            av = make_float4(t0, t1, t2, t3);
        }
        As[la_k][la_m] = av.x; As[la_k+1][la_m] = av.y;
        As[la_k+2][la_m] = av.z; As[la_k+3][la_m] = av.w;
        float4 wv = *reinterpret_cast<const float4*>(W + (size_t)(nb + la_m) * K + k0 + la_k);
        Ws[la_k][la_m] = wv.x; Ws[la_k+1][la_m] = wv.y;
        Ws[la_k+2][la_m] = wv.z; Ws[la_k+3][la_m] = wv.w;
        __syncthreads();
        #pragma unroll
        for (int k = 0; k < 16; k++) {
            float4 a = *reinterpret_cast<const float4*>(&As[k][ty << 2]);
            float4 b = *reinterpret_cast<const float4*>(&Ws[k][tx << 2]);
            acc[0][0] += a.x*b.x; acc[0][1] += a.x*b.y; acc[0][2] += a.x*b.z; acc[0][3] += a.x*b.w;
            acc[1][0] += a.y*b.x; acc[1][1] += a.y*b.y; acc[1][2] += a.y*b.z; acc[1][3] += a.y*b.w;
            acc[2][0] += a.z*b.x; acc[2][1] += a.z*b.y; acc[2][2] += a.z*b.z; acc[2][3] += a.z*b.w;
            acc[3][0] += a.w*b.x; acc[3][1] += a.w*b.y; acc[3][2] += a.w*b.z; acc[3][3] += a.w*b.w;
        }
        __syncthreads();
    }
    #pragma unroll
    for (int i = 0; i < 4; i++) {
        int m = mb + (ty << 2) + i;
        #pragma unroll
        for (int j = 0; j < 4; j++) {
            int n = nb + (tx << 2) + j;
            float v = acc[i][j] + bias[n];
            if (relu) v = fmaxf(v, 0.f);
            Cout[(size_t)m * N + n] = v;
        }
    }
}

// ---------------- GEMM-phase chunk load/store (validated layout) ----------------
struct Regs6 { uint4 v[6]; };

__device__ __forceinline__ void ldg_chunk(Regs6& R,
    const __nv_bfloat16* __restrict__ Wh, const __nv_bfloat16* __restrict__ Wl,
    const __nv_bfloat16* __restrict__ Bh, const __nv_bfloat16* __restrict__ Bl,
    int bstr, int KT, int rowbase, int k0, int koff, int tid)
{
    #pragma unroll
    for (int j = 0; j < 2; j++) {
        int seg = tid + j * 512;
        int r = seg >> 3, cs = seg & 7;
        size_t off = (size_t)(rowbase + r) * KT + k0 + cs * 8;
        R.v[j]     = *reinterpret_cast<const uint4*>(Wh + off);
        R.v[2 + j] = *reinterpret_cast<const uint4*>(Wl + off);
    }
    {
        int r = tid >> 3, cs = tid & 7;
        size_t off = (size_t)r * bstr + koff + cs * 8;
        R.v[4] = *reinterpret_cast<const uint4*>(Bh + off);
        R.v[5] = *reinterpret_cast<const uint4*>(Bl + off);
    }
}

__device__ __forceinline__ void sts_chunk(const Regs6& R, char* sm, int buf, int tid) {
    #pragma unroll
    for (int j = 0; j < 2; j++) {
        int seg = tid + j * 512;
        int r = seg >> 3, cs = seg & 7;
        uint32_t off = r * 128 + cs * 16;
        uint32_t sw = off ^ ((off >> 3) & 0x70);
        *reinterpret_cast<uint4*>(sm + SM_AWH(buf) + sw) = R.v[j];
        *reinterpret_cast<uint4*>(sm + SM_AWL(buf) + sw) = R.v[2 + j];
    }
    {
        int r = tid >> 3, cs = tid & 7;
        uint32_t off = r * 128 + cs * 16;
        uint32_t sw = off ^ ((off >> 3) & 0x70);
        *reinterpret_cast<uint4*>(sm + SM_BXH(buf) + sw) = R.v[4];
        *reinterpret_cast<uint4*>(sm + SM_BXL(buf) + sw) = R.v[5];
    }
}

// ---------------- one LSTM GEMM phase via mma.sync (bf16 3-term split) ---------
template<int L>
__device__ void gemm_phase(char* sm, uint32_t smb, int rb, int kq, int s,
    const __nv_bfloat16* __restrict__ Wh, const __nv_bfloat16* __restrict__ Wl,
    int tid)
{
    constexpr int KT = L ? 2048 : 1536;
    constexpr int NCH = L ? 8 : 6;
    const int rowbase = rb * 128;
    const int kqbase = kq * (KT / 4);

    const int warp = tid >> 5, lane = tid & 31;
    const int mt = warp >> 1;            // 0..7
    const int nh = (warp & 1) * 32;      // 0 or 32

    const int ar = mt * 16 + (lane & 15);
    const uint32_t aoff0 = (uint32_t)ar * 128 + (uint32_t)(lane >> 4) * 16;
    const uint32_t amx = (uint32_t)(ar & 7) << 4;
    const int bn0 = nh + ((lane >> 4) & 1) * 8 + (lane & 7);
    const uint32_t boff0 = (uint32_t)bn0 * 128 + (uint32_t)((lane >> 3) & 1) * 16;
    const uint32_t bmx = (uint32_t)(bn0 & 7) << 4;

    auto resolveB = [&](int k0, const __nv_bfloat16*& bh, const __nv_bfloat16*& bl,
                        int& bstr, int& koff) {
        if (L == 0) {
            if (k0 < 256)      { bh = g_ach; bl = g_acl; bstr = 256; koff = k0; }
            else if (k0 < 512) { bh = g_Ph + (size_t)s * NB * PRE;
                                 bl = g_Pl + (size_t)s * NB * PRE; bstr = 256; koff = k0 - 256; }
            else               { bh = g_h0h; bl = g_h0l; bstr = 1024; koff = k0 - 512; }
        } else {
            bstr = 1024;
            if (k0 < 1024) { bh = g_h0h; bl = g_h0l; koff = k0; }
            else           { bh = g_h1h; bl = g_h1l; koff = k0 - 1024; }
        }
    };

    float acc[4][4];
    #pragma unroll
    for (int nt = 0; nt < 4; nt++)
        #pragma unroll
        for (int q = 0; q < 4; q++) acc[nt][q] = 0.f;

    {   // prologue: chunk 0 -> buf 0
        Regs6 R; const __nv_bfloat16 *bh, *bl; int bstr, koff;
        resolveB(kqbase, bh, bl, bstr, koff);
        ldg_chunk(R, Wh, Wl, bh, bl, bstr, KT, rowbase, kqbase, koff, tid);
        sts_chunk(R, sm, 0, tid);
    }
    __syncthreads();

    for (int i = 0; i < NCH; i++) {
        Regs6 R;
        const int buf = i & 1;
        const bool more = (i + 1 < NCH);
        if (more) {
            int k0 = kqbase + (i + 1) * 64;
            const __nv_bfloat16 *bh, *bl; int bstr, koff;
            resolveB(k0, bh, bl, bstr, koff);
            ldg_chunk(R, Wh, Wl, bh, bl, bstr, KT, rowbase, k0, koff, tid);
        }
        const uint32_t awh = smb + SM_AWH(buf), awl = smb + SM_AWL(buf);
        const uint32_t bxh = smb + SM_BXH(buf), bxl = smb + SM_BXL(buf);
        #pragma unroll
        for (int kk = 0; kk < 4; kk++) {
            const uint32_t col = kk * 32;
            uint32_t ah[4], al[4], bh0[4], bh1[4], bl0[4], bl1[4];
            const uint32_t aof = (aoff0 + col) ^ amx;
            ldsm4(ah, awh + aof);
            ldsm4(al, awl + aof);
            const uint32_t bof = (boff0 + col) ^ bmx;
            ldsm4(bh0, bxh + bof);
            ldsm4(bh1, bxh + bof + 2048);
            ldsm4(bl0, bxl + bof);
            ldsm4(bl1, bxl + bof + 2048);
            mma16816(acc[0], ah, bh0[0], bh0[1]);
            mma16816(acc[1], ah, bh0[2], bh0[3]);
            mma16816(acc[2], ah, bh1[0], bh1[1]);
            mma16816(acc[3], ah, bh1[2], bh1[3]);
            mma16816(acc[0], ah, bl0[0], bl0[1]);
            mma16816(acc[1], ah, bl0[2], bl0[3]);
            mma16816(acc[2], ah, bl1[0], bl1[1]);
            mma16816(acc[3], ah, bl1[2], bl1[3]);
            mma16816(acc[0], al, bh0[0], bh0[1]);
            mma16816(acc[1], al, bh0[2], bh0[3]);
            mma16816(acc[2], al, bh1[0], bh1[1]);
            mma16816(acc[3], al, bh1[2], bh1[3]);
        }
        if (more) sts_chunk(R, sm, buf ^ 1, tid);
        __syncthreads();
    }

    // epilogue: write fp32 partials
    {
        const int trow = lane >> 2, tcol = (lane & 3) * 2;
        #pragma unroll
        for (int nt = 0; nt < 4; nt++) {
            int row = rowbase + mt * 16 + trow;
            int col = nh + nt * 8 + tcol;
            float* dst = g_part + ((size_t)kq * 4096 + row) * 64 + col;
            *reinterpret_cast<float2*>(dst) = make_float2(acc[nt][0], acc[nt][1]);
            *reinterpret_cast<float2*>(dst + 8 * 64) = make_float2(acc[nt][2], acc[nt][3]);
        }
    }
}

// ---------------- pointwise + zoneout + bf16 split ----------------
__device__ void pw_phase(int u0, const float* __restrict__ b4,
    float* __restrict__ hf, __nv_bfloat16* __restrict__ hh, __nv_bfloat16* __restrict__ hl,
    float* __restrict__ cf, int tid)
{
    int ul = tid >> 6, bat = tid & 63;
    int u = u0 + ul;
    float g[4];
    #pragma unroll
    for (int gg = 0; gg < 4; gg++) {
        int row = gg * 1024 + u;
        float v = b4[row];
        #pragma unroll
        for (int kq = 0; kq < 4; kq++)
            v += g_part[((size_t)kq * 4096 + row) * 64 + bat];
        g[gg] = v;
    }
    int idx = bat * 1024 + u;
    float cold = cf[idx], hold = hf[idx];
    float si = 1.f / (1.f + __expf(-g[0]));
    float sf = 1.f / (1.f + __expf(-g[1]));
    float so = 1.f / (1.f + __expf(-g[3]));
    float c2 = sf * cold + si * tanhf(g[2]);
    float h2 = so * tanhf(c2);
    float hn = 0.1f * hold + 0.9f * h2;
    float cn = 0.1f * cold + 0.9f * c2;
    hf[idx] = hn; cf[idx] = cn;
    __nv_bfloat16 hi = __float2bfloat16(hn);
    hh[idx] = hi;
    hl[idx] = __float2bfloat16(hn - __bfloat162float(hi));
}

// ---------------- attention: conv+energies via mma.sync ----------------
__device__ void att_step(char* sm, float* __restrict__ smf, int s, int b,
    const float* __restrict__ enc, const int* __restrict__ text_len,
    const float* __restrict__ wdec, const float* __restrict__ watt,
    const float* __restrict__ watt_b, float* __restrict__ attw_out)
{
    float* apad = smf;                  // 240
    float* dp   = smf + 240;            // 128
    float* w_s  = smf + 368;            // 128
    float* sE   = smf + 496;            // 208
    float* red  = smf + 704;            // 48
    float* hrow = smf + 768;            // 256 f4 = 1024 floats? (uses 768..1024 window? no)
    // hrow occupies smf[768..1024) only if DECD/4=256 float4 = 1024 floats -> use smf+768 as float4*?
    // place hrow at smf+768 (1024 floats -> [768..1792)) and ctx after
    float* ctx  = smf + 1792;           // 512
    int tid = threadIdx.x, lane = tid & 31, warp = tid >> 5;
    int len = text_len[b];

    if (tid < 16)  apad[tid] = 0.f;
    if (tid < 17)  apad[215 + tid] = 0.f;
    if (tid < 200) {
        float v = (s == 0) ? ((tid < len) ? 1.f / (float)len : 0.f) : g_acc[b * TE + tid];
        apad[PADC + tid] = v;
    }
    if (tid < HATT) w_s[tid] = watt[tid];
    if (tid < DECD / 4)
        reinterpret_cast<float4*>(hrow)[tid] =
            reinterpret_cast<const float4*>(g_h0f + b * DECD)[tid];
    // stage Wck bf16 tiles (rows h, stride 80 B, 32 bf16 used)
    {
        __nv_bfloat16* Ah = reinterpret_cast<__nv_bfloat16*>(sm + SM_CA_H);
        __nv_bfloat16* Al = reinterpret_cast<__nv_bfloat16*>(sm + SM_CA_L);
        for (int i = tid; i < HATT * 32; i += THR) {
            int h = i >> 5, k = i & 31;
            Ah[h * 40 + k] = g_Wckh[i];
            Al[h * 40 + k] = g_Wckl[i];
        }
    }
    __syncthreads();   // apad ready before im2col

    // im2col of apad: B[t][k] = apad[t+k] (k<31), rows 0..207 (>=200 zero), stride 80 B
    {
        __nv_bfloat16* Bh = reinterpret_cast<__nv_bfloat16*>(sm + SM_CB_H);
        __nv_bfloat16* Bl = reinterpret_cast<__nv_bfloat16*>(sm + SM_CB_L);
        for (int i = tid; i < 208 * 32; i += THR) {
            int t = i >> 5, k = i & 31;
            float v = (t < 200 && k < 31) ? apad[t + k] : 0.f;
            __nv_bfloat16 hi = __float2bfloat16(v);
            Bh[t * 40 + k] = hi;
            Bl[t * 40 + k] = __float2bfloat16(v - __bfloat162float(hi));
        }
    }

    // dp[h] = h0[b] . wdec[h]
    {
        const float4* hr4 = reinterpret_cast<const float4*>(hrow);
        for (int h = warp; h < HATT; h += 16) {
            const float4* wr = reinterpret_cast<const float4*>(wdec + (size_t)h * DECD);
            float p = 0.f;
            #pragma unroll
            for (int j = lane; j < 256; j += 32) {
                float4 w = wr[j]; float4 hv = hr4[j];
                p += w.x*hv.x + w.y*hv.y + w.z*hv.z + w.w*hv.w;
            }
            #pragma unroll
            for (int o = 16; o; o >>= 1) p += __shfl_xor_sync(0xffffffffu, p, o);
            if (lane == 0) dp[h] = p;
        }
    }
    __syncthreads();

    // conv-energy MMA: warp w handles t in [w*16, w*16+16), w < 13
    const float wb0 = watt_b[0];
    if (warp < 13) {
        const int tb = warp * 16;
        const uint32_t smb = smem_u32_of(sm);
        // B fragments (hoisted): rows t, col-operand k-major
        const int bn0 = ((lane >> 4) & 1) * 8 + (lane & 7);
        const uint32_t brow = (uint32_t)(tb + bn0) * 80 + ((lane >> 3) & 1) * 16;
        uint32_t Bhf[2][4], Blf[2][4];
        #pragma unroll
        for (int kc = 0; kc < 2; kc++) {
            ldsm4(Bhf[kc], smb + SM_CB_H + brow + kc * 32);
            ldsm4(Blf[kc], smb + SM_CB_L + brow + kc * 32);
        }
        const uint32_t arow0 = (uint32_t)(lane & 15) * 80 + (lane >> 4) * 16;
        const float* pmTb = g_pmT + (size_t)b * HATT * TE;
        float ep[2][2] = {};
        #pragma unroll
        for (int mt = 0; mt < 8; mt++) {
            float a0[4] = {}, a1[4] = {};
            #pragma unroll
            for (int kc = 0; kc < 2; kc++) {
                uint32_t ah[4], al[4];
                uint32_t aof = arow0 + (uint32_t)mt * (16 * 80) + kc * 32;
                ldsm4(ah, smb + SM_CA_H + aof);
                ldsm4(al, smb + SM_CA_L + aof);
                mma16816(a0, ah, Bhf[kc][0], Bhf[kc][1]);
                mma16816(a1, ah, Bhf[kc][2], Bhf[kc][3]);
                mma16816(a0, ah, Blf[kc][0], Blf[kc][1]);
                mma16816(a1, ah, Blf[kc][2], Blf[kc][3]);
                mma16816(a0, al, Bhf[kc][0], Bhf[kc][1]);
                mma16816(a1, al, Bhf[kc][2], Bhf[kc][3]);
            }
            // epilogue for this m-tile
            int h0 = mt * 16 + (lane >> 2), h1 = h0 + 8;
            float d0 = dp[h0], d1 = dp[h1];
            float ws0 = w_s[h0], ws1 = w_s[h1];
            #pragma unroll
            for (int j = 0; j < 2; j++) {
                int t0 = tb + j * 8;
                if (t0 < 200) {
                    int t = t0 + 2 * (lane & 3);
                    float2 p0 = *reinterpret_cast<const float2*>(pmTb + (size_t)h0 * TE + t);
                    float2 p1 = *reinterpret_cast<const float2*>(pmTb + (size_t)h1 * TE + t);
                    const float* aj = j ? a1 : a0;
                    float x, ez, th;
                    x = aj[0] + d0 + p0.x; ez = __expf(2.f * x);
                    th = 1.f - __fdividef(2.f, ez + 1.f); ep[j][0] += ws0 * th;
                    x = aj[1] + d0 + p0.y; ez = __expf(2.f * x);
                    th = 1.f - __fdividef(2.f, ez + 1.f); ep[j][1] += ws0 * th;
                    x = aj[2] + d1 + p1.x; ez = __expf(2.f * x);
                    th = 1.f - __fdividef(2.f, ez + 1.f); ep[j][0] += ws1 * th;
                    x = aj[3] + d1 + p1.y; ez = __expf(2.f * x);
                    th = 1.f - __fdividef(2.f, ez + 1.f); ep[j][1] += ws1 * th;
                }
            }
        }
        // reduce over h (lane groups stride 4) and write sE
        #pragma unroll
        for (int j = 0; j < 2; j++) {
            #pragma unroll
            for (int o = 4; o < 32; o <<= 1) {
                ep[j][0] += __shfl_xor_sync(0xffffffffu, ep[j][0], o);
                ep[j][1] += __shfl_xor_sync(0xffffffffu, ep[j][1], o);
            }
            int t0 = tb + j * 8;
            if (t0 < 200 && lane < 4) {
                sE[t0 + 2 * lane]     = ep[j][0] + wb0;
                sE[t0 + 2 * lane + 1] = ep[j][1] + wb0;
            }
        }
    }
    __syncthreads();

    // softmax over valid t (unchanged)
    float e = (tid < len) ? sE[tid] : -1e30f;
    float mx = e;
    #pragma unroll
    for (int o = 16; o; o >>= 1) mx = fmaxf(mx, __shfl_xor_sync(0xffffffffu, mx, o));
    if (lane == 0) red[warp] = mx;
    __syncthreads();
    if (tid == 0) {
        float mm = red[0];
        for (int i = 1; i < 16; i++) mm = fmaxf(mm, red[i]);
        red[16] = mm;
    }
    __syncthreads();
    mx = red[16];
    float ex = (tid < 200) ? __expf(e - mx) : 0.f;
    float sm2 = ex;
    #pragma unroll
    for (int o = 16; o; o >>= 1) sm2 += __shfl_xor_sync(0xffffffffu, sm2, o);
    if (lane == 0) red[warp] = sm2;
    __syncthreads();
    if (tid == 0) {
        float ss = 0.f;
        for (int i = 0; i < 16; i++) ss += red[i];
        red[17] = ss;
    }
    __syncthreads();
    float inv = 1.f / red[17];
    __syncthreads();
    if (tid < 200) {
        float aw = ex * inv;
        sE[tid] = aw;
        attw_out[((size_t)b * SSTEPS + s) * TE + tid] = aw;
        float an = (s == 0) ? aw : g_acc[b * TE + tid] + aw;
        g_acc[b * TE + tid] = an;
    }
    __syncthreads();

    // context: 512 threads, 2 t-halves x 256 channels
    {
        int th = tid >> 8, c = tid & 255;
        const float* er = enc + ((size_t)b * TE + th * 100) * ENCD + c;
        float a0 = 0.f, a1 = 0.f, a2 = 0.f, a3 = 0.f;
        const float* se = sE + th * 100;
        #pragma unroll 5
        for (int t = 0; t < 100; t += 4) {
            a0 += se[t]     * er[(size_t)t * ENCD];
            a1 += se[t + 1] * er[(size_t)(t + 1) * ENCD];
            a2 += se[t + 2] * er[(size_t)(t + 2) * ENCD];
            a3 += se[t + 3] * er[(size_t)(t + 3) * ENCD];
        }
        ctx[th * 256 + c] = (a0 + a1) + (a2 + a3);
    }
    __syncthreads();
    if (tid < ENCD) {
        float ac = ctx[tid] + ctx[256 + tid];
        g_acf[(size_t)(s & 1) * NB * ENCD + b * ENCD + tid] = ac;
        __nv_bfloat16 hi = __float2bfloat16(ac);
        g_ach[b * ENCD + tid] = hi;
        g_acl[b * ENCD + tid] = __float2bfloat16(ac - __bfloat162float(hi));
    }
    __syncthreads();
}

// ---------------- output projection: 4 batch-tiles x 16 row-tiles over 64 blocks -
__device__ void outproj(float* __restrict__ smf, int s, int j,
    const float* __restrict__ fw, const float* __restrict__ pwm,
    const float* __restrict__ pb, float* __restrict__ out)
{
    int tid = threadIdx.x, lane = tid & 31, wid = tid >> 5;
    int bt = j >> 4;            // batch tile (16 batches)
    int ot = j & 15;            // o-row stride class
    const float* acb = g_acf + (size_t)(s & 1) * NB * ENCD;
    float* hcs = smf;           // 16 * 1280 floats = 80 KB

    for (int i = tid; i < 16 * 320; i += THR) {
        int bb = i / 320, ii = i - bb * 320;
        int b = bt * 16 + bb;
        float4 v;
        if (ii < 256) v = reinterpret_cast<const float4*>(g_h1f + (size_t)b * DECD)[ii];
        else          v = reinterpret_cast<const float4*>(acb + (size_t)b * ENCD)[ii - 256];
        reinterpret_cast<float4*>(hcs + bb * 1280)[ii] = v;
    }
    __syncthreads();

    int nrows = (162 - ot + 15) >> 4;
    for (int task = wid; task < nrows * 2; task += 16) {
        int r = ot + (task >> 1) * 16;
        int bh = (task & 1) * 8;
        const float* row = (r < 160) ? (fw + (size_t)r * 1280) : (pwm + (size_t)(r - 160) * 1280);
        const float4* r4 = reinterpret_cast<const float4*>(row);
        float4 w[10];
        #pragma unroll
        for (int q = 0; q < 10; q++) w[q] = r4[lane + q * 32];
        #pragma unroll
        for (int bb = 0; bb < 8; bb++) {
            const float4* h4 = reinterpret_cast<const float4*>(hcs + (size_t)(bh + bb) * 1280);
            float sum = 0.f;
            #pragma unroll
            for (int q = 0; q < 10; q++) {
                float4 hv = h4[lane + q * 32];
                sum += w[q].x*hv.x + w[q].y*hv.y + w[q].z*hv.z + w[q].w*hv.w;
            }
            #pragma unroll
            for (int of = 16; of; of >>= 1) sum += __shfl_xor_sync(0xffffffffu, sum, of);
            if (lane == 0) {
                int b = bt * 16 + bh + bb;
                if (r < 160) {
                    int rr = r / NC, ch = r - rr * NC;
                    out[(size_t)b * NC * TFEAT + (size_t)ch * TFEAT + s * 2 + rr] = sum;
                } else {
                    out[LOGIT_OFF + (size_t)b * TFEAT + s * 2 + (r - 160)] = sum + pb[r - 160];
                }
            }
        }
    }
    __syncthreads();
}

// ---------------- persistent decoder ----------------
__global__ void __launch_bounds__(THR, 1) k_decoder(
    const float* __restrict__ enc, const int* __restrict__ tlen,
    const float* __restrict__ wdec, const float* __restrict__ watt,
    const float* __restrict__ wattb,
    const float* __restrict__ fow, const float* __restrict__ pow_,
    const float* __restrict__ pob, float* __restrict__ out)
{
    extern __shared__ char sm[];
    float* smf = reinterpret_cast<float*>(sm) + SM_F_OFF;
    uint32_t smb = smem_u32_of(sm);
    int tid = threadIdx.x;
    int blk = blockIdx.x;
    int rb = blk >> 2, kq = blk & 3;
    float* attw = out + ATTW_OFF;
    unsigned gen = 0;

    // phase 0: attention for step 0 (h0 = 0, uniform prior)
    if (blk < 64)
        att_step(sm, smf, 0, blk, enc, tlen, wdec, watt, wattb, attw);
    gen++; gbar(gen);

    for (int s = 0; s < SSTEPS; s++) {
        // A: lstm0 GEMM
        gemm_phase<0>(sm, smb, rb, kq, s, g_W0h, g_W0l, tid);
        gen++; gbar(gen);
        // B: pw0 (all) + outproj(s-1) on blocks >= 64
        pw_phase(blk * 8, g_b40, g_h0f, g_h0h, g_h0l, g_c0, tid);
        if (blk >= 64 && s >= 1)
            outproj(smf, s - 1, blk - 64, fow, pow_, pob, out);
        gen++; gbar(gen);
        // C: lstm1 GEMM
        gemm_phase<1>(sm, smb, rb, kq, s, g_W1h, g_W1l, tid);
        gen++; gbar(gen);
        // D: pw1 (all) + attention(s+1) on blocks < 64
        pw_phase(blk * 8, g_b41, g_h1f, g_h1h, g_h1l, g_c1, tid);
        if (blk < 64 && s + 1 < SSTEPS)
            att_step(sm, smf, s + 1, blk, enc, tlen, wdec, watt, wattb, attw);
        gen++; gbar(gen);
    }
    // tail: outproj for the last step
    if (blk >= 64)
        outproj(smf, SSTEPS - 1, blk - 64, fow, pow_, pob, out);
}

// ---------------- host ----------------
static float* symaddr(const void* sym) {
    void* p = nullptr;
    cudaGetSymbolAddress(&p, sym);
    return (float*)p;
}

extern "C" void kernel_launch(void* const* d_in, const int* in_sizes, int n_in,
                              void* d_out, int out_size)
{
    const float* enc    = (const float*)d_in[0];
    const int*   tlen   = (const int*)  d_in[1];
    const float* ft     = (const float*)d_in[2];
    const float* enc_w  = (const float*)d_in[3];
    const float* enc_b  = (const float*)d_in[4];
    const float* dec_w  = (const float*)d_in[5];
    const float* att_w  = (const float*)d_in[6];
    const float* conv_w = (const float*)d_in[7];
    const float* ww     = (const float*)d_in[8];
    const float* wbb    = (const float*)d_in[9];
    const float* pw0    = (const float*)d_in[10];
    const float* pb0    = (const float*)d_in[11];
    const float* pw1    = (const float*)d_in[12];
    const float* pb1    = (const float*)d_in[13];
    const float* l0wih  = (const float*)d_in[14];
    const float* l0whh  = (const float*)d_in[15];
    const float* l0bih  = (const float*)d_in[16];
    const float* l0bhh  = (const float*)d_in[17];
    const float* l1wih  = (const float*)d_in[18];
    const float* l1whh  = (const float*)d_in[19];
    const float* l1bih  = (const float*)d_in[20];
    const float* l1bhh  = (const float*)d_in[21];
    const float* fow    = (const float*)d_in[22];
    const float* pow_   = (const float*)d_in[23];
    const float* pob    = (const float*)d_in[24];
    float* out = (float*)d_out;

    float* pm_p = symaddr(g_pm);
    float* preH = symaddr(g_preH);
    float* Pp   = symaddr(g_P);

    static int smem_set = 0;
    if (!smem_set) {
        cudaFuncSetAttribute(k_decoder, cudaFuncAttributeMaxDynamicSharedMemorySize, SM_TOTAL);
        smem_set = 1;
    }

    k_setup<<<(HSZ + 255) / 256, 256>>>(att_w, conv_w, l0bih, l0bhh, l1bih, l1bhh);
    k_gemm<0><<<dim3(200, 2), 256>>>(enc, enc_w, enc_b, pm_p, 128, 256, 256, nullptr, 0);
    k_gemm<1><<<dim3(500, 4), 256>>>(nullptr, pw0, pb0, preH, 256, 160, 0, ft, 1);
    k_gemm<0><<<dim3(500, 4), 256>>>(preH, pw1, pb1, Pp, 256, 256, 256, nullptr, 1);
    k_cvtAll<<<(N_W0 + N_W1 + N_P + N_PM + 255) / 256, 256>>>(l0wih, l0whh, l1wih, l1whh);

    k_decoder<<<GRID, THR, SM_TOTAL>>>(
        enc, tlen, dec_w, ww, wbb, fow, pow_, pob, out);
}

// round 15
// speedup vs baseline: 1.1711x; 1.0077x over previous
#include <cuda_runtime.h>
#include <cuda_bf16.h>
#include <cstdint>

#define NB    64
#define TE    200
#define ENCD  256
#define DECD  1024
#define HATT  128
#define NCONV 32
#define KCONV 31
#define PADC  15
#define PRE   256
#define NC    80
#define TFEAT 1000
#define SSTEPS 500
#define HSZ   (NB*DECD)

#define LOGIT_OFF 5120000
#define ATTW_OFF  5184000

#define GRID  128
#define THR   512

// dynamic smem (bytes): double-buffered W(hi/lo) 128x64 bf16 + act(hi/lo) 64x64 bf16
#define SM_AWH(b)  (1024  + (b)*16384)
#define SM_AWL(b)  (33792 + (b)*16384)
#define SM_BXH(b)  (66560 + (b)*8192)
#define SM_BXL(b)  (82944 + (b)*8192)
#define SM_TOTAL   99328
#define SM_F_OFF   256      // float index of att/outproj scratch (byte 1024)

// att conv-MMA smem layout (bytes; reuses GEMM buffer space)
#define SM_CA_H   8192      // Wck hi: 128 rows x 80 B
#define SM_CA_L   18432     // Wck lo
#define SM_CB_H   28672     // im2col apad hi: 208 rows x 80 B
#define SM_CB_L   45312     // im2col apad lo

// ---------------- scratch ----------------
__device__ float g_pm[NB*TE*HATT];
__device__ float g_pmT[NB*HATT*TE];     // [b][h][t]
__device__ __nv_bfloat16 g_Wckh[HATT*32], g_Wckl[HATT*32];
__device__ float g_preH[SSTEPS*NB*PRE];
__device__ __nv_bfloat16 g_Ph[SSTEPS*NB*PRE], g_Pl[SSTEPS*NB*PRE];
__device__ __nv_bfloat16 g_W0h[4096*1536], g_W0l[4096*1536];
__device__ __nv_bfloat16 g_W1h[4096*2048], g_W1l[4096*2048];
__device__ float g_part[4*4096*64];      // [kq][row][batch]
__device__ float g_acf[2*NB*ENCD];
__device__ __nv_bfloat16 g_ach[NB*ENCD], g_acl[NB*ENCD];
__device__ float g_h0f[HSZ], g_c0[HSZ];
__device__ float g_h1f[HSZ], g_c1[HSZ];
__device__ __nv_bfloat16 g_h0h[HSZ], g_h0l[HSZ], g_h1h[HSZ], g_h1l[HSZ];
__device__ float g_acc[NB*TE];
__device__ float g_b40[4096], g_b41[4096];
__device__ unsigned g_flags[GRID];

// ---------------- warp MMA helpers (portable sm_80+) ----------------
__device__ __forceinline__ uint32_t smem_u32_of(const void* p) {
    uint32_t a;
    asm("{ .reg .u64 t; cvta.to.shared.u64 t, %1; cvt.u32.u64 %0, t; }" : "=r"(a) : "l"(p));
    return a;
}
__device__ __forceinline__ void ldsm4(uint32_t* r, uint32_t addr) {
    asm volatile("ldmatrix.sync.aligned.m8n8.x4.shared.b16 {%0,%1,%2,%3}, [%4];"
        : "=r"(r[0]), "=r"(r[1]), "=r"(r[2]), "=r"(r[3]) : "r"(addr));
}
__device__ __forceinline__ void mma16816(float* c, const uint32_t* a, uint32_t b0, uint32_t b1) {
    asm volatile("mma.sync.aligned.m16n8k16.row.col.f32.bf16.bf16.f32 "
        "{%0,%1,%2,%3}, {%4,%5,%6,%7}, {%8,%9}, {%0,%1,%2,%3};"
        : "+f"(c[0]), "+f"(c[1]), "+f"(c[2]), "+f"(c[3])
        : "r"(a[0]), "r"(a[1]), "r"(a[2]), "r"(a[3]), "r"(b0), "r"(b1));
}

// ---------------- grid barrier: per-block flags + pure-spin poll ----------------
__device__ __forceinline__ void gbar(unsigned gen) {
    __syncthreads();
    if (threadIdx.x == 0) {
        __threadfence();
        *((volatile unsigned*)&g_flags[blockIdx.x]) = gen;
    }
    if (threadIdx.x < GRID) {
        volatile unsigned* f = g_flags + threadIdx.x;
        while (*f < gen) { }
    }
    __threadfence();
    __syncthreads();
}

// ---------------- launch #0: merged setup (init + all weight splits) -----------
#define N_W0 (4096*1536)
#define N_W1 (4096*2048)
__global__ void k_setup(const float* __restrict__ watt, const float* __restrict__ cw,
                        const float* __restrict__ b0a, const float* __restrict__ b0b,
                        const float* __restrict__ b1a, const float* __restrict__ b1b,
                        const float* __restrict__ l0wih, const float* __restrict__ l0whh,
                        const float* __restrict__ l1wih, const float* __restrict__ l1whh) {
    int g0 = blockIdx.x * blockDim.x + threadIdx.x;
    int stride = gridDim.x * blockDim.x;
    for (int i = g0; i < N_W0; i += stride) {
        int r = i / 1536, k = i - r * 1536;
        float v = (k < 512) ? l0wih[(size_t)r * 512 + k] : l0whh[(size_t)r * 1024 + (k - 512)];
        __nv_bfloat16 hi = __float2bfloat16(v);
        g_W0h[i] = hi;
        g_W0l[i] = __float2bfloat16(v - __bfloat162float(hi));
    }
    for (int i = g0; i < N_W1; i += stride) {
        int r = i / 2048, k = i - r * 2048;
        float v = (k < 1024) ? l1wih[(size_t)r * 1024 + k] : l1whh[(size_t)r * 1024 + (k - 1024)];
        __nv_bfloat16 hi = __float2bfloat16(v);
        g_W1h[i] = hi;
        g_W1l[i] = __float2bfloat16(v - __bfloat162float(hi));
    }
    for (int i = g0; i < HSZ; i += stride) {
        g_h0f[i] = 0.f; g_h1f[i] = 0.f; g_c0[i] = 0.f; g_c1[i] = 0.f;
        __nv_bfloat16 z = __float2bfloat16(0.f);
        g_h0h[i] = z; g_h0l[i] = z; g_h1h[i] = z; g_h1l[i] = z;
    }
    for (int i = g0; i < 4096; i += stride) {
        g_b40[i] = b0a[i] + b0b[i]; g_b41[i] = b1a[i] + b1b[i];
    }
    for (int i = g0; i < HATT * 32; i += stride) {
        int h = i >> 5, k = i & 31;
        float s = 0.f;
        if (k < KCONV) {
            #pragma unroll
            for (int c = 0; c < NCONV; c++) s += watt[h * NCONV + c] * cw[c * KCONV + k];
        }
        __nv_bfloat16 hi = __float2bfloat16(s);
        g_Wckh[i] = hi;
        g_Wckl[i] = __float2bfloat16(s - __bfloat162float(hi));
    }
    for (int i = g0; i < GRID; i += stride) g_flags[i] = 0u;
}

// ---------------- setup GEMM body (validated):  C = A*W^T (+bias, relu) --------
// EPI 0: plain fp32 store. EPI 1: enc — also write g_pmT. EPI 2: bf16 hi/lo split.
template<int LOADER, int EPI>
__device__ void gemm_body(
    const float* __restrict__ A, const float* __restrict__ W,
    const float* __restrict__ bias, float* __restrict__ Cout,
    int N, int K, int lda, const float* __restrict__ ft, int relu,
    int mbi, int nbi)
{
    __shared__ float As[16][68];
    __shared__ float Ws[16][68];
    int tid  = threadIdx.x;
    int mb = mbi * 64, nb = nbi * 64;
    int la_m = tid >> 2, la_k = (tid & 3) << 2;
    int tx = tid & 15, ty = tid >> 4;
    float acc[4][4] = {};

    for (int k0 = 0; k0 < K; k0 += 16) {
        float4 av;
        if (LOADER == 0) {
            av = *reinterpret_cast<const float4*>(A + (size_t)(mb + la_m) * lda + k0 + la_k);
        } else {
            int row = mb + la_m;
            int s = row >> 6, bb = row & 63;
            float t0 = 0.f, t1 = 0.f, t2 = 0.f, t3 = 0.f;
            if (s > 0) {
                int base = (s - 1) * 2;
                int k = k0 + la_k;
                const float* fb = ft + (size_t)bb * NC * TFEAT;
                t0 = fb[(k % NC) * TFEAT + base + k / NC]; k++;
                t1 = fb[(k % NC) * TFEAT + base + k / NC]; k++;
                t2 = fb[(k % NC) * TFEAT + base + k / NC]; k++;
                t3 = fb[(k % NC) * TFEAT + base + k / NC];
            }
            av = make_float4(t0, t1, t2, t3);
        }
        As[la_k][la_m] = av.x; As[la_k+1][la_m] = av.y;
        As[la_k+2][la_m] = av.z; As[la_k+3][la_m] = av.w;
        float4 wv = *reinterpret_cast<const float4*>(W + (size_t)(nb + la_m) * K + k0 + la_k);
        Ws[la_k][la_m] = wv.x; Ws[la_k+1][la_m] = wv.y;
        Ws[la_k+2][la_m] = wv.z; Ws[la_k+3][la_m] = wv.w;
        __syncthreads();
        #pragma unroll
        for (int k = 0; k < 16; k++) {
            float4 a = *reinterpret_cast<const float4*>(&As[k][ty << 2]);
            float4 b = *reinterpret_cast<const float4*>(&Ws[k][tx << 2]);
            acc[0][0] += a.x*b.x; acc[0][1] += a.x*b.y; acc[0][2] += a.x*b.z; acc[0][3] += a.x*b.w;
            acc[1][0] += a.y*b.x; acc[1][1] += a.y*b.y; acc[1][2] += a.y*b.z; acc[1][3] += a.y*b.w;
            acc[2][0] += a.z*b.x; acc[2][1] += a.z*b.y; acc[2][2] += a.z*b.z; acc[2][3] += a.z*b.w;
            acc[3][0] += a.w*b.x; acc[3][1] += a.w*b.y; acc[3][2] += a.w*b.z; acc[3][3] += a.w*b.w;
        }
        __syncthreads();
    }
    #pragma unroll
    for (int i = 0; i < 4; i++) {
        int m = mb + (ty << 2) + i;
        #pragma unroll
        for (int j = 0; j < 4; j++) {
            int n = nb + (tx << 2) + j;
            float v = acc[i][j] + bias[n];
            if (relu) v = fmaxf(v, 0.f);
            if (EPI == 2) {
                __nv_bfloat16 hi = __float2bfloat16(v);
                g_Ph[(size_t)m * 256 + n] = hi;
                g_Pl[(size_t)m * 256 + n] = __float2bfloat16(v - __bfloat162float(hi));
            } else {
                Cout[(size_t)m * N + n] = v;
                if (EPI == 1) {
                    int b = m / TE, t = m - b * TE;
                    g_pmT[((size_t)b * HATT + n) * TE + t] = v;
                }
            }
        }
    }
}

// launch #1: enc projection (bx<200, by<2) || prenet layer 1 (bx>=200)
__global__ __launch_bounds__(256) void k_gemmA(
    const float* __restrict__ enc, const float* __restrict__ enc_w,
    const float* __restrict__ enc_b,
    const float* __restrict__ ft, const float* __restrict__ pw0,
    const float* __restrict__ pb0)
{
    if (blockIdx.x < 200) {
        if (blockIdx.y < 2)
            gemm_body<0, 1>(enc, enc_w, enc_b, g_pm, 128, 256, 256, nullptr, 0,
                            blockIdx.x, blockIdx.y);
    } else {
        gemm_body<1, 0>(nullptr, pw0, pb0, g_preH, 256, 160, 0, ft, 1,
                        blockIdx.x - 200, blockIdx.y);
    }
}

// launch #2: prenet layer 2 -> bf16 hi/lo directly
__global__ __launch_bounds__(256) void k_gemmB(
    const float* __restrict__ pw1, const float* __restrict__ pb1)
{
    gemm_body<0, 2>(g_preH, pw1, pb1, nullptr, 256, 256, 256, nullptr, 1,
                    blockIdx.x, blockIdx.y);
}

// ---------------- GEMM-phase chunk load/store (validated layout) ----------------
struct Regs6 { uint4 v[6]; };

__device__ __forceinline__ void ldg_chunk(Regs6& R,
    const __nv_bfloat16* __restrict__ Wh, const __nv_bfloat16* __restrict__ Wl,
    const __nv_bfloat16* __restrict__ Bh, const __nv_bfloat16* __restrict__ Bl,
    int bstr, int KT, int rowbase, int k0, int koff, int tid)
{
    #pragma unroll
    for (int j = 0; j < 2; j++) {
        int seg = tid + j * 512;
        int r = seg >> 3, cs = seg & 7;
        size_t off = (size_t)(rowbase + r) * KT + k0 + cs * 8;
        R.v[j]     = *reinterpret_cast<const uint4*>(Wh + off);
        R.v[2 + j] = *reinterpret_cast<const uint4*>(Wl + off);
    }
    {
        int r = tid >> 3, cs = tid & 7;
        size_t off = (size_t)r * bstr + koff + cs * 8;
        R.v[4] = *reinterpret_cast<const uint4*>(Bh + off);
        R.v[5] = *reinterpret_cast<const uint4*>(Bl + off);
    }
}

__device__ __forceinline__ void sts_chunk(const Regs6& R, char* sm, int buf, int tid) {
    #pragma unroll
    for (int j = 0; j < 2; j++) {
        int seg = tid + j * 512;
        int r = seg >> 3, cs = seg & 7;
        uint32_t off = r * 128 + cs * 16;
        uint32_t sw = off ^ ((off >> 3) & 0x70);
        *reinterpret_cast<uint4*>(sm + SM_AWH(buf) + sw) = R.v[j];
        *reinterpret_cast<uint4*>(sm + SM_AWL(buf) + sw) = R.v[2 + j];
    }
    {
        int r = tid >> 3, cs = tid & 7;
        uint32_t off = r * 128 + cs * 16;
        uint32_t sw = off ^ ((off >> 3) & 0x70);
        *reinterpret_cast<uint4*>(sm + SM_BXH(buf) + sw) = R.v[4];
        *reinterpret_cast<uint4*>(sm + SM_BXL(buf) + sw) = R.v[5];
    }
}

// ---------------- one LSTM GEMM phase via mma.sync (bf16 3-term split) ---------
template<int L>
__device__ void gemm_phase(char* sm, uint32_t smb, int rb, int kq, int s,
    const __nv_bfloat16* __restrict__ Wh, const __nv_bfloat16* __restrict__ Wl,
    int tid)
{
    constexpr int KT = L ? 2048 : 1536;
    constexpr int NCH = L ? 8 : 6;
    const int rowbase = rb * 128;
    const int kqbase = kq * (KT / 4);

    const int warp = tid >> 5, lane = tid & 31;
    const int mt = warp >> 1;            // 0..7
    const int nh = (warp & 1) * 32;      // 0 or 32

    const int ar = mt * 16 + (lane & 15);
    const uint32_t aoff0 = (uint32_t)ar * 128 + (uint32_t)(lane >> 4) * 16;
    const uint32_t amx = (uint32_t)(ar & 7) << 4;
    const int bn0 = nh + ((lane >> 4) & 1) * 8 + (lane & 7);
    const uint32_t boff0 = (uint32_t)bn0 * 128 + (uint32_t)((lane >> 3) & 1) * 16;
    const uint32_t bmx = (uint32_t)(bn0 & 7) << 4;

    auto resolveB = [&](int k0, const __nv_bfloat16*& bh, const __nv_bfloat16*& bl,
                        int& bstr, int& koff) {
        if (L == 0) {
            if (k0 < 256)      { bh = g_ach; bl = g_acl; bstr = 256; koff = k0; }
            else if (k0 < 512) { bh = g_Ph + (size_t)s * NB * PRE;
                                 bl = g_Pl + (size_t)s * NB * PRE; bstr = 256; koff = k0 - 256; }
            else               { bh = g_h0h; bl = g_h0l; bstr = 1024; koff = k0 - 512; }
        } else {
            bstr = 1024;
            if (k0 < 1024) { bh = g_h0h; bl = g_h0l; koff = k0; }
            else           { bh = g_h1h; bl = g_h1l; koff = k0 - 1024; }
        }
    };

    float acc[4][4];
    #pragma unroll
    for (int nt = 0; nt < 4; nt++)
        #pragma unroll
        for (int q = 0; q < 4; q++) acc[nt][q] = 0.f;

    {   // prologue: chunk 0 -> buf 0
        Regs6 R; const __nv_bfloat16 *bh, *bl; int bstr, koff;
        resolveB(kqbase, bh, bl, bstr, koff);
        ldg_chunk(R, Wh, Wl, bh, bl, bstr, KT, rowbase, kqbase, koff, tid);
        sts_chunk(R, sm, 0, tid);
    }
    __syncthreads();

    for (int i = 0; i < NCH; i++) {
        Regs6 R;
        const int buf = i & 1;
        const bool more = (i + 1 < NCH);
        if (more) {
            int k0 = kqbase + (i + 1) * 64;
            const __nv_bfloat16 *bh, *bl; int bstr, koff;
            resolveB(k0, bh, bl, bstr, koff);
            ldg_chunk(R, Wh, Wl, bh, bl, bstr, KT, rowbase, k0, koff, tid);
        }
        const uint32_t awh = smb + SM_AWH(buf), awl = smb + SM_AWL(buf);
        const uint32_t bxh = smb + SM_BXH(buf), bxl = smb + SM_BXL(buf);
        #pragma unroll
        for (int kk = 0; kk < 4; kk++) {
            const uint32_t col = kk * 32;
            uint32_t ah[4], al[4], bh0[4], bh1[4], bl0[4], bl1[4];
            const uint32_t aof = (aoff0 + col) ^ amx;
            ldsm4(ah, awh + aof);
            ldsm4(al, awl + aof);
            const uint32_t bof = (boff0 + col) ^ bmx;
            ldsm4(bh0, bxh + bof);
            ldsm4(bh1, bxh + bof + 2048);
            ldsm4(bl0, bxl + bof);
            ldsm4(bl1, bxl + bof + 2048);
            mma16816(acc[0], ah, bh0[0], bh0[1]);
            mma16816(acc[1], ah, bh0[2], bh0[3]);
            mma16816(acc[2], ah, bh1[0], bh1[1]);
            mma16816(acc[3], ah, bh1[2], bh1[3]);
            mma16816(acc[0], ah, bl0[0], bl0[1]);
            mma16816(acc[1], ah, bl0[2], bl0[3]);
            mma16816(acc[2], ah, bl1[0], bl1[1]);
            mma16816(acc[3], ah, bl1[2], bl1[3]);
            mma16816(acc[0], al, bh0[0], bh0[1]);
            mma16816(acc[1], al, bh0[2], bh0[3]);
            mma16816(acc[2], al, bh1[0], bh1[1]);
            mma16816(acc[3], al, bh1[2], bh1[3]);
        }
        if (more) sts_chunk(R, sm, buf ^ 1, tid);
        __syncthreads();
    }

    // epilogue: write fp32 partials
    {
        const int trow = lane >> 2, tcol = (lane & 3) * 2;
        #pragma unroll
        for (int nt = 0; nt < 4; nt++) {
            int row = rowbase + mt * 16 + trow;
            int col = nh + nt * 8 + tcol;
            float* dst = g_part + ((size_t)kq * 4096 + row) * 64 + col;
            *reinterpret_cast<float2*>(dst) = make_float2(acc[nt][0], acc[nt][1]);
            *reinterpret_cast<float2*>(dst + 8 * 64) = make_float2(acc[nt][2], acc[nt][3]);
        }
    }
}

// ---------------- pointwise + zoneout + bf16 split ----------------
__device__ void pw_phase(int u0, const float* __restrict__ b4,
    float* __restrict__ hf, __nv_bfloat16* __restrict__ hh, __nv_bfloat16* __restrict__ hl,
    float* __restrict__ cf, int tid)
{
    int ul = tid >> 6, bat = tid & 63;
    int u = u0 + ul;
    float g[4];
    #pragma unroll
    for (int gg = 0; gg < 4; gg++) {
        int row = gg * 1024 + u;
        float v = b4[row];
        #pragma unroll
        for (int kq = 0; kq < 4; kq++)
            v += g_part[((size_t)kq * 4096 + row) * 64 + bat];
        g[gg] = v;
    }
    int idx = bat * 1024 + u;
    float cold = cf[idx], hold = hf[idx];
    float si = 1.f / (1.f + __expf(-g[0]));
    float sf = 1.f / (1.f + __expf(-g[1]));
    float so = 1.f / (1.f + __expf(-g[3]));
    float c2 = sf * cold + si * tanhf(g[2]);
    float h2 = so * tanhf(c2);
    float hn = 0.1f * hold + 0.9f * h2;
    float cn = 0.1f * cold + 0.9f * c2;
    hf[idx] = hn; cf[idx] = cn;
    __nv_bfloat16 hi = __float2bfloat16(hn);
    hh[idx] = hi;
    hl[idx] = __float2bfloat16(hn - __bfloat162float(hi));
}

// ---------------- attention: conv+energies via mma.sync (validated R13) --------
__device__ void att_step(char* sm, float* __restrict__ smf, int s, int b,
    const float* __restrict__ enc, const int* __restrict__ text_len,
    const float* __restrict__ wdec, const float* __restrict__ watt,
    const float* __restrict__ watt_b, float* __restrict__ attw_out)
{
    float* apad = smf;                  // 240
    float* dp   = smf + 240;            // 128
    float* w_s  = smf + 368;            // 128
    float* sE   = smf + 496;            // 208
    float* red  = smf + 704;            // 48
    float* hrow = smf + 768;            // 1024
    float* ctx  = smf + 1792;           // 512
    int tid = threadIdx.x, lane = tid & 31, warp = tid >> 5;
    int len = text_len[b];

    if (tid < 16)  apad[tid] = 0.f;
    if (tid < 17)  apad[215 + tid] = 0.f;
    if (tid < 200) {
        float v = (s == 0) ? ((tid < len) ? 1.f / (float)len : 0.f) : g_acc[b * TE + tid];
        apad[PADC + tid] = v;
    }
    if (tid < HATT) w_s[tid] = watt[tid];
    if (tid < DECD / 4)
        reinterpret_cast<float4*>(hrow)[tid] =
            reinterpret_cast<const float4*>(g_h0f + b * DECD)[tid];
    {
        __nv_bfloat16* Ah = reinterpret_cast<__nv_bfloat16*>(sm + SM_CA_H);
        __nv_bfloat16* Al = reinterpret_cast<__nv_bfloat16*>(sm + SM_CA_L);
        for (int i = tid; i < HATT * 32; i += THR) {
            int h = i >> 5, k = i & 31;
            Ah[h * 40 + k] = g_Wckh[i];
            Al[h * 40 + k] = g_Wckl[i];
        }
    }
    __syncthreads();   // apad ready before im2col

    {
        __nv_bfloat16* Bh = reinterpret_cast<__nv_bfloat16*>(sm + SM_CB_H);
        __nv_bfloat16* Bl = reinterpret_cast<__nv_bfloat16*>(sm + SM_CB_L);
        for (int i = tid; i < 208 * 32; i += THR) {
            int t = i >> 5, k = i & 31;
            float v = (t < 200 && k < 31) ? apad[t + k] : 0.f;
            __nv_bfloat16 hi = __float2bfloat16(v);
            Bh[t * 40 + k] = hi;
            Bl[t * 40 + k] = __float2bfloat16(v - __bfloat162float(hi));
        }
    }

    {
        const float4* hr4 = reinterpret_cast<const float4*>(hrow);
        for (int h = warp; h < HATT; h += 16) {
            const float4* wr = reinterpret_cast<const float4*>(wdec + (size_t)h * DECD);
            float p = 0.f;
            #pragma unroll
            for (int j = lane; j < 256; j += 32) {
                float4 w = wr[j]; float4 hv = hr4[j];
                p += w.x*hv.x + w.y*hv.y + w.z*hv.z + w.w*hv.w;
            }
            #pragma unroll
            for (int o = 16; o; o >>= 1) p += __shfl_xor_sync(0xffffffffu, p, o);
            if (lane == 0) dp[h] = p;
        }
    }
    __syncthreads();

    const float wb0 = watt_b[0];
    if (warp < 13) {
        const int tb = warp * 16;
        const uint32_t smb = smem_u32_of(sm);
        const int bn0 = ((lane >> 4) & 1) * 8 + (lane & 7);
        const uint32_t brow = (uint32_t)(tb + bn0) * 80 + ((lane >> 3) & 1) * 16;
        uint32_t Bhf[2][4], Blf[2][4];
        #pragma unroll
        for (int kc = 0; kc < 2; kc++) {
            ldsm4(Bhf[kc], smb + SM_CB_H + brow + kc * 32);
            ldsm4(Blf[kc], smb + SM_CB_L + brow + kc * 32);
        }
        const uint32_t arow0 = (uint32_t)(lane & 15) * 80 + (lane >> 4) * 16;
        const float* pmTb = g_pmT + (size_t)b * HATT * TE;
        float ep[2][2] = {};
        #pragma unroll
        for (int mt = 0; mt < 8; mt++) {
            float a0[4] = {}, a1[4] = {};
            #pragma unroll
            for (int kc = 0; kc < 2; kc++) {
                uint32_t ah[4], al[4];
                uint32_t aof = arow0 + (uint32_t)mt * (16 * 80) + kc * 32;
                ldsm4(ah, smb + SM_CA_H + aof);
                ldsm4(al, smb + SM_CA_L + aof);
                mma16816(a0, ah, Bhf[kc][0], Bhf[kc][1]);
                mma16816(a1, ah, Bhf[kc][2], Bhf[kc][3]);
                mma16816(a0, ah, Blf[kc][0], Blf[kc][1]);
                mma16816(a1, ah, Blf[kc][2], Blf[kc][3]);
                mma16816(a0, al, Bhf[kc][0], Bhf[kc][1]);
                mma16816(a1, al, Bhf[kc][2], Bhf[kc][3]);
            }
            int h0 = mt * 16 + (lane >> 2), h1 = h0 + 8;
            float d0 = dp[h0], d1 = dp[h1];
            float ws0 = w_s[h0], ws1 = w_s[h1];
            #pragma unroll
            for (int j = 0; j < 2; j++) {
                int t0 = tb + j * 8;
                if (t0 < 200) {
                    int t = t0 + 2 * (lane & 3);
                    float2 p0 = *reinterpret_cast<const float2*>(pmTb + (size_t)h0 * TE + t);
                    float2 p1 = *reinterpret_cast<const float2*>(pmTb + (size_t)h1 * TE + t);
                    const float* aj = j ? a1 : a0;
                    float x, ez, th;
                    x = aj[0] + d0 + p0.x; ez = __expf(2.f * x);
                    th = 1.f - __fdividef(2.f, ez + 1.f); ep[j][0] += ws0 * th;
                    x = aj[1] + d0 + p0.y; ez = __expf(2.f * x);
                    th = 1.f - __fdividef(2.f, ez + 1.f); ep[j][1] += ws0 * th;
                    x = aj[2] + d1 + p1.x; ez = __expf(2.f * x);
                    th = 1.f - __fdividef(2.f, ez + 1.f); ep[j][0] += ws1 * th;
                    x = aj[3] + d1 + p1.y; ez = __expf(2.f * x);
                    th = 1.f - __fdividef(2.f, ez + 1.f); ep[j][1] += ws1 * th;
                }
            }
        }
        #pragma unroll
        for (int j = 0; j < 2; j++) {
            #pragma unroll
            for (int o = 4; o < 32; o <<= 1) {
                ep[j][0] += __shfl_xor_sync(0xffffffffu, ep[j][0], o);
                ep[j][1] += __shfl_xor_sync(0xffffffffu, ep[j][1], o);
            }
            int t0 = tb + j * 8;
            if (t0 < 200 && lane < 4) {
                sE[t0 + 2 * lane]     = ep[j][0] + wb0;
                sE[t0 + 2 * lane + 1] = ep[j][1] + wb0;
            }
        }
    }
    __syncthreads();

    float e = (tid < len) ? sE[tid] : -1e30f;
    float mx = e;
    #pragma unroll
    for (int o = 16; o; o >>= 1) mx = fmaxf(mx, __shfl_xor_sync(0xffffffffu, mx, o));
    if (lane == 0) red[warp] = mx;
    __syncthreads();
    if (tid == 0) {
        float mm = red[0];
        for (int i = 1; i < 16; i++) mm = fmaxf(mm, red[i]);
        red[16] = mm;
    }
    __syncthreads();
    mx = red[16];
    float ex = (tid < 200) ? __expf(e - mx) : 0.f;
    float sm2 = ex;
    #pragma unroll
    for (int o = 16; o; o >>= 1) sm2 += __shfl_xor_sync(0xffffffffu, sm2, o);
    if (lane == 0) red[warp] = sm2;
    __syncthreads();
    if (tid == 0) {
        float ss = 0.f;
        for (int i = 0; i < 16; i++) ss += red[i];
        red[17] = ss;
    }
    __syncthreads();
    float inv = 1.f / red[17];
    __syncthreads();
    if (tid < 200) {
        float aw = ex * inv;
        sE[tid] = aw;
        attw_out[((size_t)b * SSTEPS + s) * TE + tid] = aw;
        float an = (s == 0) ? aw : g_acc[b * TE + tid] + aw;
        g_acc[b * TE + tid] = an;
    }
    __syncthreads();

    {
        int th = tid >> 8, c = tid & 255;
        const float* er = enc + ((size_t)b * TE + th * 100) * ENCD + c;
        float a0 = 0.f, a1 = 0.f, a2 = 0.f, a3 = 0.f;
        const float* se = sE + th * 100;
        #pragma unroll 5
        for (int t = 0; t < 100; t += 4) {
            a0 += se[t]     * er[(size_t)t * ENCD];
            a1 += se[t + 1] * er[(size_t)(t + 1) * ENCD];
            a2 += se[t + 2] * er[(size_t)(t + 2) * ENCD];
            a3 += se[t + 3] * er[(size_t)(t + 3) * ENCD];
        }
        ctx[th * 256 + c] = (a0 + a1) + (a2 + a3);
    }
    __syncthreads();
    if (tid < ENCD) {
        float ac = ctx[tid] + ctx[256 + tid];
        g_acf[(size_t)(s & 1) * NB * ENCD + b * ENCD + tid] = ac;
        __nv_bfloat16 hi = __float2bfloat16(ac);
        g_ach[b * ENCD + tid] = hi;
        g_acl[b * ENCD + tid] = __float2bfloat16(ac - __bfloat162float(hi));
    }
    __syncthreads();
}

// ---------------- output projection (validated R12) ----------------
__device__ void outproj(float* __restrict__ smf, int s, int j,
    const float* __restrict__ fw, const float* __restrict__ pwm,
    const float* __restrict__ pb, float* __restrict__ out)
{
    int tid = threadIdx.x, lane = tid & 31, wid = tid >> 5;
    int bt = j >> 4;
    int ot = j & 15;
    const float* acb = g_acf + (size_t)(s & 1) * NB * ENCD;
    float* hcs = smf;

    for (int i = tid; i < 16 * 320; i += THR) {
        int bb = i / 320, ii = i - bb * 320;
        int b = bt * 16 + bb;
        float4 v;
        if (ii < 256) v = reinterpret_cast<const float4*>(g_h1f + (size_t)b * DECD)[ii];
        else          v = reinterpret_cast<const float4*>(acb + (size_t)b * ENCD)[ii - 256];
        reinterpret_cast<float4*>(hcs + bb * 1280)[ii] = v;
    }
    __syncthreads();

    int nrows = (162 - ot + 15) >> 4;
    for (int task = wid; task < nrows * 2; task += 16) {
        int r = ot + (task >> 1) * 16;
        int bh = (task & 1) * 8;
        const float* row = (r < 160) ? (fw + (size_t)r * 1280) : (pwm + (size_t)(r - 160) * 1280);
        const float4* r4 = reinterpret_cast<const float4*>(row);
        float4 w[10];
        #pragma unroll
        for (int q = 0; q < 10; q++) w[q] = r4[lane + q * 32];
        #pragma unroll
        for (int bb = 0; bb < 8; bb++) {
            const float4* h4 = reinterpret_cast<const float4*>(hcs + (size_t)(bh + bb) * 1280);
            float sum = 0.f;
            #pragma unroll
            for (int q = 0; q < 10; q++) {
                float4 hv = h4[lane + q * 32];
                sum += w[q].x*hv.x + w[q].y*hv.y + w[q].z*hv.z + w[q].w*hv.w;
            }
            #pragma unroll
            for (int of = 16; of; of >>= 1) sum += __shfl_xor_sync(0xffffffffu, sum, of);
            if (lane == 0) {
                int b = bt * 16 + bh + bb;
                if (r < 160) {
                    int rr = r / NC, ch = r - rr * NC;
                    out[(size_t)b * NC * TFEAT + (size_t)ch * TFEAT + s * 2 + rr] = sum;
                } else {
                    out[LOGIT_OFF + (size_t)b * TFEAT + s * 2 + (r - 160)] = sum + pb[r - 160];
                }
            }
        }
    }
    __syncthreads();
}

// ---------------- persistent decoder (launch #3) ----------------
__global__ void __launch_bounds__(THR, 1) k_decoder(
    const float* __restrict__ enc, const int* __restrict__ tlen,
    const float* __restrict__ wdec, const float* __restrict__ watt,
    const float* __restrict__ wattb,
    const float* __restrict__ fow, const float* __restrict__ pow_,
    const float* __restrict__ pob, float* __restrict__ out)
{
    extern __shared__ char sm[];
    float* smf = reinterpret_cast<float*>(sm) + SM_F_OFF;
    uint32_t smb = smem_u32_of(sm);
    int tid = threadIdx.x;
    int blk = blockIdx.x;
    int rb = blk >> 2, kq = blk & 3;
    float* attw = out + ATTW_OFF;
    unsigned gen = 0;

    if (blk < 64)
        att_step(sm, smf, 0, blk, enc, tlen, wdec, watt, wattb, attw);
    gen++; gbar(gen);

    for (int s = 0; s < SSTEPS; s++) {
        gemm_phase<0>(sm, smb, rb, kq, s, g_W0h, g_W0l, tid);
        gen++; gbar(gen);
        pw_phase(blk * 8, g_b40, g_h0f, g_h0h, g_h0l, g_c0, tid);
        if (blk >= 64 && s >= 1)
            outproj(smf, s - 1, blk - 64, fow, pow_, pob, out);
        gen++; gbar(gen);
        gemm_phase<1>(sm, smb, rb, kq, s, g_W1h, g_W1l, tid);
        gen++; gbar(gen);
        pw_phase(blk * 8, g_b41, g_h1f, g_h1h, g_h1l, g_c1, tid);
        if (blk < 64 && s + 1 < SSTEPS)
            att_step(sm, smf, s + 1, blk, enc, tlen, wdec, watt, wattb, attw);
        gen++; gbar(gen);
    }
    if (blk >= 64)
        outproj(smf, SSTEPS - 1, blk - 64, fow, pow_, pob, out);
}

// ---------------- host ----------------
extern "C" void kernel_launch(void* const* d_in, const int* in_sizes, int n_in,
                              void* d_out, int out_size)
{
    const float* enc    = (const float*)d_in[0];
    const int*   tlen   = (const int*)  d_in[1];
    const float* ft     = (const float*)d_in[2];
    const float* enc_w  = (const float*)d_in[3];
    const float* enc_b  = (const float*)d_in[4];
    const float* dec_w  = (const float*)d_in[5];
    const float* att_w  = (const float*)d_in[6];
    const float* conv_w = (const float*)d_in[7];
    const float* ww     = (const float*)d_in[8];
    const float* wbb    = (const float*)d_in[9];
    const float* pw0    = (const float*)d_in[10];
    const float* pb0    = (const float*)d_in[11];
    const float* pw1    = (const float*)d_in[12];
    const float* pb1    = (const float*)d_in[13];
    const float* l0wih  = (const float*)d_in[14];
    const float* l0whh  = (const float*)d_in[15];
    const float* l0bih  = (const float*)d_in[16];
    const float* l0bhh  = (const float*)d_in[17];
    const float* l1wih  = (const float*)d_in[18];
    const float* l1whh  = (const float*)d_in[19];
    const float* l1bih  = (const float*)d_in[20];
    const float* l1bhh  = (const float*)d_in[21];
    const float* fow    = (const float*)d_in[22];
    const float* pow_   = (const float*)d_in[23];
    const float* pob    = (const float*)d_in[24];
    float* out = (float*)d_out;

    static int smem_set = 0;
    if (!smem_set) {
        cudaFuncSetAttribute(k_decoder, cudaFuncAttributeMaxDynamicSharedMemorySize, SM_TOTAL);
        smem_set = 1;
    }

    // launch indices: 0 setup, 1 gemmA, 2 gemmB, 3 k_decoder (ncu captures #3)
    k_setup<<<2048, 256>>>(att_w, conv_w, l0bih, l0bhh, l1bih, l1bhh,
                           l0wih, l0whh, l1wih, l1whh);
    k_gemmA<<<dim3(700, 4), 256>>>(enc, enc_w, enc_b, ft, pw0, pb0);
    k_gemmB<<<dim3(500, 4), 256>>>(pw1, pb1);
    k_decoder<<<GRID, THR, SM_TOTAL>>>(
        enc, tlen, dec_w, ww, wbb, fow, pow_, pob, out);
}

// round 17
// speedup vs baseline: 1.5833x; 1.3520x over previous
#include <cuda_runtime.h>
#include <cuda_bf16.h>
#include <cstdint>

#define NB    64
#define TE    200
#define ENCD  256
#define DECD  1024
#define HATT  128
#define NCONV 32
#define KCONV 31
#define PADC  15
#define PRE   256
#define NC    80
#define TFEAT 1000
#define SSTEPS 500
#define HSZ   (NB*DECD)

#define LOGIT_OFF 5120000
#define ATTW_OFF  5184000

#define GRID  128
#define THR   512

// dynamic smem: 4-stage pipeline buffers, 24576 B each: WH(4K) WL(4K) BH(8K) BL(8K)
#define SM_ST(b)   (1024 + (b)*24576)
#define SM_TOTAL   99328
#define SM_F_OFF   256      // float index of att/outproj scratch (byte 1024)

// att conv-MMA smem layout (bytes; reuses pipeline buffer space after syncs)
#define SM_CA_H   8192
#define SM_CA_L   18432
#define SM_CB_H   28672
#define SM_CB_L   45312

// ---------------- scratch ----------------
__device__ float g_pm[NB*TE*HATT];
__device__ float g_pmT[NB*HATT*TE];
__device__ __nv_bfloat16 g_Wckh[HATT*32], g_Wckl[HATT*32];
__device__ float g_preH[SSTEPS*NB*PRE];
__device__ __nv_bfloat16 g_Ph[SSTEPS*NB*PRE], g_Pl[SSTEPS*NB*PRE];
__device__ __nv_bfloat16 g_W0h[4096*1536], g_W0l[4096*1536];
__device__ __nv_bfloat16 g_W1h[4096*2048], g_W1l[4096*2048];
__device__ float g_acf[4*NB*ENCD];                 // 4-slot
__device__ __nv_bfloat16 g_ach[NB*ENCD], g_acl[NB*ENCD];
__device__ float g_h0f[2*HSZ], g_c0[HSZ];          // h double-buffered (slot = parity)
__device__ float g_h1f[2*HSZ], g_c1[HSZ];
__device__ __nv_bfloat16 g_h0h[2*HSZ], g_h0l[2*HSZ], g_h1h[2*HSZ], g_h1l[2*HSZ];
__device__ float g_acc[NB*TE];
__device__ float g_b40[4096], g_b41[4096];
__device__ unsigned g_flags[GRID];

// ---------------- PTX helpers ----------------
__device__ __forceinline__ uint32_t smem_u32_of(const void* p) {
    uint32_t a;
    asm("{ .reg .u64 t; cvta.to.shared.u64 t, %1; cvt.u32.u64 %0, t; }" : "=r"(a) : "l"(p));
    return a;
}
__device__ __forceinline__ void ldsm4(uint32_t* r, uint32_t addr) {
    asm volatile("ldmatrix.sync.aligned.m8n8.x4.shared.b16 {%0,%1,%2,%3}, [%4];"
        : "=r"(r[0]), "=r"(r[1]), "=r"(r[2]), "=r"(r[3]) : "r"(addr));
}
__device__ __forceinline__ void mma16816(float* c, const uint32_t* a, uint32_t b0, uint32_t b1) {
    asm volatile("mma.sync.aligned.m16n8k16.row.col.f32.bf16.bf16.f32 "
        "{%0,%1,%2,%3}, {%4,%5,%6,%7}, {%8,%9}, {%0,%1,%2,%3};"
        : "+f"(c[0]), "+f"(c[1]), "+f"(c[2]), "+f"(c[3])
        : "r"(a[0]), "r"(a[1]), "r"(a[2]), "r"(a[3]), "r"(b0), "r"(b1));
}
#define CP16(dst, src) \
    asm volatile("cp.async.cg.shared.global [%0], [%1], 16;" :: "r"(dst), "l"(src) : "memory")
#define CP_COMMIT() asm volatile("cp.async.commit_group;" ::: "memory")
#define CP_WAIT2()  asm volatile("cp.async.wait_group 2;" ::: "memory")
#define CP_WAIT0()  asm volatile("cp.async.wait_group 0;" ::: "memory")

// ---------------- grid barrier (validated R11+) ----------------
__device__ __forceinline__ void gbar(unsigned gen) {
    __syncthreads();
    if (threadIdx.x == 0) {
        __threadfence();
        *((volatile unsigned*)&g_flags[blockIdx.x]) = gen;
    }
    if (threadIdx.x < GRID) {
        volatile unsigned* f = g_flags + threadIdx.x;
        while (*f < gen) { }
    }
    __threadfence();
    __syncthreads();
}

// ---------------- launch #0: merged setup ----------------
#define N_W0 (4096*1536)
#define N_W1 (4096*2048)
__global__ void k_setup(const float* __restrict__ watt, const float* __restrict__ cw,
                        const float* __restrict__ b0a, const float* __restrict__ b0b,
                        const float* __restrict__ b1a, const float* __restrict__ b1b,
                        const float* __restrict__ l0wih, const float* __restrict__ l0whh,
                        const float* __restrict__ l1wih, const float* __restrict__ l1whh) {
    int g0 = blockIdx.x * blockDim.x + threadIdx.x;
    int stride = gridDim.x * blockDim.x;
    for (int i = g0; i < N_W0; i += stride) {
        int r = i / 1536, k = i - r * 1536;
        float v = (k < 512) ? l0wih[(size_t)r * 512 + k] : l0whh[(size_t)r * 1024 + (k - 512)];
        __nv_bfloat16 hi = __float2bfloat16(v);
        g_W0h[i] = hi;
        g_W0l[i] = __float2bfloat16(v - __bfloat162float(hi));
    }
    for (int i = g0; i < N_W1; i += stride) {
        int r = i / 2048, k = i - r * 2048;
        float v = (k < 1024) ? l1wih[(size_t)r * 1024 + k] : l1whh[(size_t)r * 1024 + (k - 1024)];
        __nv_bfloat16 hi = __float2bfloat16(v);
        g_W1h[i] = hi;
        g_W1l[i] = __float2bfloat16(v - __bfloat162float(hi));
    }
    for (int i = g0; i < 2 * HSZ; i += stride) {
        g_h0f[i] = 0.f; g_h1f[i] = 0.f;
        __nv_bfloat16 z = __float2bfloat16(0.f);
        g_h0h[i] = z; g_h0l[i] = z; g_h1h[i] = z; g_h1l[i] = z;
    }
    for (int i = g0; i < HSZ; i += stride) { g_c0[i] = 0.f; g_c1[i] = 0.f; }
    for (int i = g0; i < 4096; i += stride) {
        g_b40[i] = b0a[i] + b0b[i]; g_b41[i] = b1a[i] + b1b[i];
    }
    for (int i = g0; i < HATT * 32; i += stride) {
        int h = i >> 5, k = i & 31;
        float s = 0.f;
        if (k < KCONV) {
            #pragma unroll
            for (int c = 0; c < NCONV; c++) s += watt[h * NCONV + c] * cw[c * KCONV + k];
        }
        __nv_bfloat16 hi = __float2bfloat16(s);
        g_Wckh[i] = hi;
        g_Wckl[i] = __float2bfloat16(s - __bfloat162float(hi));
    }
    for (int i = g0; i < GRID; i += stride) g_flags[i] = 0u;
}

// ---------------- setup GEMM body (validated) ----------------
template<int LOADER, int EPI>
__device__ void gemm_body(
    const float* __restrict__ A, const float* __restrict__ W,
    const float* __restrict__ bias, float* __restrict__ Cout,
    int N, int K, int lda, const float* __restrict__ ft, int relu,
    int mbi, int nbi)
{
    __shared__ float As[16][68];
    __shared__ float Ws[16][68];
    int tid  = threadIdx.x;
    int mb = mbi * 64, nb = nbi * 64;
    int la_m = tid >> 2, la_k = (tid & 3) << 2;
    int tx = tid & 15, ty = tid >> 4;
    float acc[4][4] = {};

    for (int k0 = 0; k0 < K; k0 += 16) {
        float4 av;
        if (LOADER == 0) {
            av = *reinterpret_cast<const float4*>(A + (size_t)(mb + la_m) * lda + k0 + la_k);
        } else {
            int row = mb + la_m;
            int s = row >> 6, bb = row & 63;
            float t0 = 0.f, t1 = 0.f, t2 = 0.f, t3 = 0.f;
            if (s > 0) {
                int base = (s - 1) * 2;
                int k = k0 + la_k;
                const float* fb = ft + (size_t)bb * NC * TFEAT;
                t0 = fb[(k % NC) * TFEAT + base + k / NC]; k++;
                t1 = fb[(k % NC) * TFEAT + base + k / NC]; k++;
                t2 = fb[(k % NC) * TFEAT + base + k / NC]; k++;
                t3 = fb[(k % NC) * TFEAT + base + k / NC];
            }
            av = make_float4(t0, t1, t2, t3);
        }
        As[la_k][la_m] = av.x; As[la_k+1][la_m] = av.y;
        As[la_k+2][la_m] = av.z; As[la_k+3][la_m] = av.w;
        float4 wv = *reinterpret_cast<const float4*>(W + (size_t)(nb + la_m) * K + k0 + la_k);
        Ws[la_k][la_m] = wv.x; Ws[la_k+1][la_m] = wv.y;
        Ws[la_k+2][la_m] = wv.z; Ws[la_k+3][la_m] = wv.w;
        __syncthreads();
        #pragma unroll
        for (int k = 0; k < 16; k++) {
            float4 a = *reinterpret_cast<const float4*>(&As[k][ty << 2]);
            float4 b = *reinterpret_cast<const float4*>(&Ws[k][tx << 2]);
            acc[0][0] += a.x*b.x; acc[0][1] += a.x*b.y; acc[0][2] += a.x*b.z; acc[0][3] += a.x*b.w;
            acc[1][0] += a.y*b.x; acc[1][1] += a.y*b.y; acc[1][2] += a.y*b.z; acc[1][3] += a.y*b.w;
            acc[2][0] += a.z*b.x; acc[2][1] += a.z*b.y; acc[2][2] += a.z*b.z; acc[2][3] += a.z*b.w;
            acc[3][0] += a.w*b.x; acc[3][1] += a.w*b.y; acc[3][2] += a.w*b.z; acc[3][3] += a.w*b.w;
        }
        __syncthreads();
    }
    #pragma unroll
    for (int i = 0; i < 4; i++) {
        int m = mb + (ty << 2) + i;
        #pragma unroll
        for (int j = 0; j < 4; j++) {
            int n = nb + (tx << 2) + j;
            float v = acc[i][j] + bias[n];
            if (relu) v = fmaxf(v, 0.f);
            if (EPI == 2) {
                __nv_bfloat16 hi = __float2bfloat16(v);
                g_Ph[(size_t)m * 256 + n] = hi;
                g_Pl[(size_t)m * 256 + n] = __float2bfloat16(v - __bfloat162float(hi));
            } else {
                Cout[(size_t)m * N + n] = v;
                if (EPI == 1) {
                    int b = m / TE, t = m - b * TE;
                    g_pmT[((size_t)b * HATT + n) * TE + t] = v;
                }
            }
        }
    }
}

__global__ __launch_bounds__(256) void k_gemmA(
    const float* __restrict__ enc, const float* __restrict__ enc_w,
    const float* __restrict__ enc_b,
    const float* __restrict__ ft, const float* __restrict__ pw0,
    const float* __restrict__ pb0)
{
    if (blockIdx.x < 200) {
        if (blockIdx.y < 2)
            gemm_body<0, 1>(enc, enc_w, enc_b, g_pm, 128, 256, 256, nullptr, 0,
                            blockIdx.x, blockIdx.y);
    } else {
        gemm_body<1, 0>(nullptr, pw0, pb0, g_preH, 256, 160, 0, ft, 1,
                        blockIdx.x - 200, blockIdx.y);
    }
}

__global__ __launch_bounds__(256) void k_gemmB(
    const float* __restrict__ pw1, const float* __restrict__ pb1)
{
    gemm_body<0, 2>(g_preH, pw1, pb1, nullptr, 256, 256, 256, nullptr, 1,
                    blockIdx.x, blockIdx.y);
}

// ---------------- fused LSTM phase: full-K GEMM (cp.async 4-stage) + pointwise --
// Block rb owns units [rb*8, rb*8+8): rows {g*1024 + rb*8 + j}. 16 warps =
// 4 K-groups x (2 m-halves x 2 n-halves). In-block smem reduction, pw inline.
template<int L>
__device__ void lstm_phase(char* sm, uint32_t smb, int rb, int s, int p,
    const __nv_bfloat16* __restrict__ Wh, const __nv_bfloat16* __restrict__ Wl,
    const float* __restrict__ b4,
    const float* __restrict__ hprev_f, float* __restrict__ hout_f,
    __nv_bfloat16* __restrict__ hout_h, __nv_bfloat16* __restrict__ hout_l,
    float* __restrict__ cio, int tid)
{
    constexpr int KT  = L ? 2048 : 1536;
    constexpr int NCH = KT / 64;
    const int warp = tid >> 5, lane = tid & 31;
    const int kg = warp >> 2, wm = (warp >> 1) & 1, wn = warp & 1;

    // cp.async segment geometry (per thread, constant over chunks)
    const int sW = tid & 255, rw = sW >> 3, csW = sW & 7;
    const bool loW = tid >= 256;
    const __nv_bfloat16* WsrcB = (loW ? Wl : Wh)
        + (size_t)((rw >> 3) * 1024 + rb * 8 + (rw & 7)) * KT + csW * 8;
    const uint32_t wdst = (loW ? 4096u : 0u)
        + (uint32_t)(((rw * 128 + csW * 16)) ^ ((rw & 7) << 4));
    const int rowb = tid >> 3, csB = tid & 7;
    const uint32_t bdst = 8192u + (uint32_t)((rowb * 128 + csB * 16) ^ ((rowb & 7) << 4));
    const size_t bofs = (size_t)csB * 8;

    auto issue = [&](int c) {
        int k0 = c * 64;
        uint32_t st = smb + SM_ST(c & 3);
        CP16(st + wdst, WsrcB + k0);
        const __nv_bfloat16 *bh, *bl;
        if (L == 0) {
            if (k0 < 256)      { bh = g_ach + rowb * 256 + k0 + bofs;
                                 bl = g_acl + rowb * 256 + k0 + bofs; }
            else if (k0 < 512) { size_t o = (size_t)s * NB * PRE + rowb * 256 + (k0 - 256) + bofs;
                                 bh = g_Ph + o; bl = g_Pl + o; }
            else               { size_t o = (size_t)p * HSZ + rowb * 1024 + (k0 - 512) + bofs;
                                 bh = g_h0h + o; bl = g_h0l + o; }
        } else {
            if (k0 < 1024) { size_t o = (size_t)(p ^ 1) * HSZ + rowb * 1024 + k0 + bofs;
                             bh = g_h0h + o; bl = g_h0l + o; }
            else           { size_t o = (size_t)p * HSZ + rowb * 1024 + (k0 - 1024) + bofs;
                             bh = g_h1h + o; bl = g_h1l + o; }
        }
        CP16(st + bdst, bh);
        CP16(st + bdst + 8192, bl);
    };

    // MMA fragment addressing (constant)
    const int ar = wm * 16 + (lane & 15);
    const uint32_t aoff = (uint32_t)((ar * 128 + (lane >> 4) * 16 + kg * 32) ^ ((ar & 7) << 4));
    const int bn0 = wn * 32 + ((lane >> 4) & 1) * 8 + (lane & 7);
    const uint32_t boff = (uint32_t)((bn0 * 128 + ((lane >> 3) & 1) * 16 + kg * 32)
                                     ^ ((bn0 & 7) << 4));

    float acc[4][4];
    #pragma unroll
    for (int nt = 0; nt < 4; nt++)
        #pragma unroll
        for (int q = 0; q < 4; q++) acc[nt][q] = 0.f;

    issue(0); CP_COMMIT();
    issue(1); CP_COMMIT();
    issue(2); CP_COMMIT();

    for (int i = 0; i < NCH; i++) {
        CP_WAIT2();
        __syncthreads();
        if (i + 3 < NCH) issue(i + 3);
        CP_COMMIT();
        uint32_t st = smb + SM_ST(i & 3);
        uint32_t ah[4], al[4], bh0[4], bh1[4], bl0[4], bl1[4];
        ldsm4(ah, st + aoff);
        ldsm4(al, st + 4096 + aoff);
        ldsm4(bh0, st + 8192 + boff);
        ldsm4(bh1, st + 8192 + boff + 2048);
        ldsm4(bl0, st + 16384 + boff);
        ldsm4(bl1, st + 16384 + boff + 2048);
        mma16816(acc[0], ah, bh0[0], bh0[1]);
        mma16816(acc[1], ah, bh0[2], bh0[3]);
        mma16816(acc[2], ah, bh1[0], bh1[1]);
        mma16816(acc[3], ah, bh1[2], bh1[3]);
        mma16816(acc[0], ah, bl0[0], bl0[1]);
        mma16816(acc[1], ah, bl0[2], bl0[3]);
        mma16816(acc[2], ah, bl1[0], bl1[1]);
        mma16816(acc[3], ah, bl1[2], bl1[3]);
        mma16816(acc[0], al, bh0[0], bh0[1]);
        mma16816(acc[1], al, bh0[2], bh0[3]);
        mma16816(acc[2], al, bh1[0], bh1[1]);
        mma16816(acc[3], al, bh1[2], bh1[3]);
    }
    CP_WAIT0();
    __syncthreads();

    // in-block reduction: part[kgroup 4][row 32][batch 64] fp32 (32 KB at byte 1024)
    float* part = reinterpret_cast<float*>(sm + 1024);
    {
        const int trow = lane >> 2, tcol = (lane & 3) * 2;
        #pragma unroll
        for (int nt = 0; nt < 4; nt++) {
            int r = kg * 32 + wm * 16 + trow;
            int c = wn * 32 + nt * 8 + tcol;
            float* dst = part + (size_t)r * 64 + c;
            *reinterpret_cast<float2*>(dst) = make_float2(acc[nt][0], acc[nt][1]);
            *reinterpret_cast<float2*>(dst + 8 * 64) = make_float2(acc[nt][2], acc[nt][3]);
        }
    }
    __syncthreads();

    // pointwise + zoneout: thread = (unit j, batch)
    {
        int j = tid >> 6, bat = tid & 63;
        int u = rb * 8 + j;
        float g[4];
        #pragma unroll
        for (int gg = 0; gg < 4; gg++) {
            float v = b4[gg * 1024 + u];
            #pragma unroll
            for (int k2 = 0; k2 < 4; k2++)
                v += part[(size_t)(k2 * 32 + gg * 8 + j) * 64 + bat];
            g[gg] = v;
        }
        int idx = bat * 1024 + u;
        float cold = cio[idx], hold = hprev_f[idx];
        float si = 1.f / (1.f + __expf(-g[0]));
        float sf = 1.f / (1.f + __expf(-g[1]));
        float so = 1.f / (1.f + __expf(-g[3]));
        float c2 = sf * cold + si * tanhf(g[2]);
        float h2 = so * tanhf(c2);
        float hn = 0.1f * hold + 0.9f * h2;
        float cn = 0.1f * cold + 0.9f * c2;
        hout_f[idx] = hn; cio[idx] = cn;
        __nv_bfloat16 hi = __float2bfloat16(hn);
        hout_h[idx] = hi;
        hout_l[idx] = __float2bfloat16(hn - __bfloat162float(hi));
    }
    __syncthreads();
}

// ---------------- attention (validated R13/R15; h0 slot passed in) ------------
__device__ void att_step(char* sm, float* __restrict__ smf, int s, int b,
    const float* __restrict__ enc, const int* __restrict__ text_len,
    const float* __restrict__ wdec, const float* __restrict__ watt,
    const float* __restrict__ watt_b, float* __restrict__ attw_out,
    const float* __restrict__ h0row)
{
    float* apad = smf;                  // 240
    float* dp   = smf + 240;            // 128
    float* w_s  = smf + 368;            // 128
    float* sE   = smf + 496;            // 208
    float* red  = smf + 704;            // 48
    float* hrow = smf + 768;            // 1024
    float* ctx  = smf + 1792;           // 512
    int tid = threadIdx.x, lane = tid & 31, warp = tid >> 5;
    int len = text_len[b];

    if (tid < 16)  apad[tid] = 0.f;
    if (tid < 17)  apad[215 + tid] = 0.f;
    if (tid < 200) {
        float v = (s == 0) ? ((tid < len) ? 1.f / (float)len : 0.f) : g_acc[b * TE + tid];
        apad[PADC + tid] = v;
    }
    if (tid < HATT) w_s[tid] = watt[tid];
    if (tid < DECD / 4)
        reinterpret_cast<float4*>(hrow)[tid] =
            reinterpret_cast<const float4*>(h0row + b * DECD)[tid];
    {
        __nv_bfloat16* Ah = reinterpret_cast<__nv_bfloat16*>(sm + SM_CA_H);
        __nv_bfloat16* Al = reinterpret_cast<__nv_bfloat16*>(sm + SM_CA_L);
        for (int i = tid; i < HATT * 32; i += THR) {
            int h = i >> 5, k = i & 31;
            Ah[h * 40 + k] = g_Wckh[i];
            Al[h * 40 + k] = g_Wckl[i];
        }
    }
    __syncthreads();

    {
        __nv_bfloat16* Bh = reinterpret_cast<__nv_bfloat16*>(sm + SM_CB_H);
        __nv_bfloat16* Bl = reinterpret_cast<__nv_bfloat16*>(sm + SM_CB_L);
        for (int i = tid; i < 208 * 32; i += THR) {
            int t = i >> 5, k = i & 31;
            float v = (t < 200 && k < 31) ? apad[t + k] : 0.f;
            __nv_bfloat16 hi = __float2bfloat16(v);
            Bh[t * 40 + k] = hi;
            Bl[t * 40 + k] = __float2bfloat16(v - __bfloat162float(hi));
        }
    }

    {
        const float4* hr4 = reinterpret_cast<const float4*>(hrow);
        for (int h = warp; h < HATT; h += 16) {
            const float4* wr = reinterpret_cast<const float4*>(wdec + (size_t)h * DECD);
            float pz = 0.f;
            #pragma unroll
            for (int j = lane; j < 256; j += 32) {
                float4 w = wr[j]; float4 hv = hr4[j];
                pz += w.x*hv.x + w.y*hv.y + w.z*hv.z + w.w*hv.w;
            }
            #pragma unroll
            for (int o = 16; o; o >>= 1) pz += __shfl_xor_sync(0xffffffffu, pz, o);
            if (lane == 0) dp[h] = pz;
        }
    }
    __syncthreads();

    const float wb0 = watt_b[0];
    if (warp < 13) {
        const int tb = warp * 16;
        const uint32_t smb = smem_u32_of(sm);
        const int bn0 = ((lane >> 4) & 1) * 8 + (lane & 7);
        const uint32_t brow = (uint32_t)(tb + bn0) * 80 + ((lane >> 3) & 1) * 16;
        uint32_t Bhf[2][4], Blf[2][4];
        #pragma unroll
        for (int kc = 0; kc < 2; kc++) {
            ldsm4(Bhf[kc], smb + SM_CB_H + brow + kc * 32);
            ldsm4(Blf[kc], smb + SM_CB_L + brow + kc * 32);
        }
        const uint32_t arow0 = (uint32_t)(lane & 15) * 80 + (lane >> 4) * 16;
        const float* pmTb = g_pmT + (size_t)b * HATT * TE;
        float ep[2][2] = {};
        #pragma unroll
        for (int mt = 0; mt < 8; mt++) {
            float a0[4] = {}, a1[4] = {};
            #pragma unroll
            for (int kc = 0; kc < 2; kc++) {
                uint32_t ah[4], al[4];
                uint32_t aof = arow0 + (uint32_t)mt * (16 * 80) + kc * 32;
                ldsm4(ah, smb + SM_CA_H + aof);
                ldsm4(al, smb + SM_CA_L + aof);
                mma16816(a0, ah, Bhf[kc][0], Bhf[kc][1]);
                mma16816(a1, ah, Bhf[kc][2], Bhf[kc][3]);
                mma16816(a0, ah, Blf[kc][0], Blf[kc][1]);
                mma16816(a1, ah, Blf[kc][2], Blf[kc][3]);
                mma16816(a0, al, Bhf[kc][0], Bhf[kc][1]);
                mma16816(a1, al, Bhf[kc][2], Bhf[kc][3]);
            }
            int h0 = mt * 16 + (lane >> 2), h1 = h0 + 8;
            float d0 = dp[h0], d1 = dp[h1];
            float ws0 = w_s[h0], ws1 = w_s[h1];
            #pragma unroll
            for (int j = 0; j < 2; j++) {
                int t0 = tb + j * 8;
                if (t0 < 200) {
                    int t = t0 + 2 * (lane & 3);
                    float2 p0 = *reinterpret_cast<const float2*>(pmTb + (size_t)h0 * TE + t);
                    float2 p1 = *reinterpret_cast<const float2*>(pmTb + (size_t)h1 * TE + t);
                    const float* aj = j ? a1 : a0;
                    float x, ez, th;
                    x = aj[0] + d0 + p0.x; ez = __expf(2.f * x);
                    th = 1.f - __fdividef(2.f, ez + 1.f); ep[j][0] += ws0 * th;
                    x = aj[1] + d0 + p0.y; ez = __expf(2.f * x);
                    th = 1.f - __fdividef(2.f, ez + 1.f); ep[j][1] += ws0 * th;
                    x = aj[2] + d1 + p1.x; ez = __expf(2.f * x);
                    th = 1.f - __fdividef(2.f, ez + 1.f); ep[j][0] += ws1 * th;
                    x = aj[3] + d1 + p1.y; ez = __expf(2.f * x);
                    th = 1.f - __fdividef(2.f, ez + 1.f); ep[j][1] += ws1 * th;
                }
            }
        }
        #pragma unroll
        for (int j = 0; j < 2; j++) {
            #pragma unroll
            for (int o = 4; o < 32; o <<= 1) {
                ep[j][0] += __shfl_xor_sync(0xffffffffu, ep[j][0], o);
                ep[j][1] += __shfl_xor_sync(0xffffffffu, ep[j][1], o);
            }
            int t0 = tb + j * 8;
            if (t0 < 200 && lane < 4) {
                sE[t0 + 2 * lane]     = ep[j][0] + wb0;
                sE[t0 + 2 * lane + 1] = ep[j][1] + wb0;
            }
        }
    }
    __syncthreads();

    float e = (tid < len) ? sE[tid] : -1e30f;
    float mx = e;
    #pragma unroll
    for (int o = 16; o; o >>= 1) mx = fmaxf(mx, __shfl_xor_sync(0xffffffffu, mx, o));
    if (lane == 0) red[warp] = mx;
    __syncthreads();
    if (tid == 0) {
        float mm = red[0];
        for (int i = 1; i < 16; i++) mm = fmaxf(mm, red[i]);
        red[16] = mm;
    }
    __syncthreads();
    mx = red[16];
    float ex = (tid < 200) ? __expf(e - mx) : 0.f;
    float sm2 = ex;
    #pragma unroll
    for (int o = 16; o; o >>= 1) sm2 += __shfl_xor_sync(0xffffffffu, sm2, o);
    if (lane == 0) red[warp] = sm2;
    __syncthreads();
    if (tid == 0) {
        float ss = 0.f;
        for (int i = 0; i < 16; i++) ss += red[i];
        red[17] = ss;
    }
    __syncthreads();
    float inv = 1.f / red[17];
    __syncthreads();
    if (tid < 200) {
        float aw = ex * inv;
        sE[tid] = aw;
        attw_out[((size_t)b * SSTEPS + s) * TE + tid] = aw;
        float an = (s == 0) ? aw : g_acc[b * TE + tid] + aw;
        g_acc[b * TE + tid] = an;
    }
    __syncthreads();

    {
        int th = tid >> 8, c = tid & 255;
        const float* er = enc + ((size_t)b * TE + th * 100) * ENCD + c;
        float a0 = 0.f, a1 = 0.f, a2 = 0.f, a3 = 0.f;
        const float* se = sE + th * 100;
        #pragma unroll 5
        for (int t = 0; t < 100; t += 4) {
            a0 += se[t]     * er[(size_t)t * ENCD];
            a1 += se[t + 1] * er[(size_t)(t + 1) * ENCD];
            a2 += se[t + 2] * er[(size_t)(t + 2) * ENCD];
            a3 += se[t + 3] * er[(size_t)(t + 3) * ENCD];
        }
        ctx[th * 256 + c] = (a0 + a1) + (a2 + a3);
    }
    __syncthreads();
    if (tid < ENCD) {
        float ac = ctx[tid] + ctx[256 + tid];
        g_acf[(size_t)(s & 3) * NB * ENCD + b * ENCD + tid] = ac;
        __nv_bfloat16 hi = __float2bfloat16(ac);
        g_ach[b * ENCD + tid] = hi;
        g_acl[b * ENCD + tid] = __float2bfloat16(ac - __bfloat162float(hi));
    }
    __syncthreads();
}

// ---------------- output projection (validated R12; h1 slot passed in) ---------
__device__ void outproj(float* __restrict__ smf, int s, int j,
    const float* __restrict__ fw, const float* __restrict__ pwm,
    const float* __restrict__ pb, float* __restrict__ out,
    const float* __restrict__ h1row)
{
    int tid = threadIdx.x, lane = tid & 31, wid = tid >> 5;
    int bt = j >> 4;
    int ot = j & 15;
    const float* acb = g_acf + (size_t)(s & 3) * NB * ENCD;
    float* hcs = smf;

    for (int i = tid; i < 16 * 320; i += THR) {
        int bb = i / 320, ii = i - bb * 320;
        int b = bt * 16 + bb;
        float4 v;
        if (ii < 256) v = reinterpret_cast<const float4*>(h1row + (size_t)b * DECD)[ii];
        else          v = reinterpret_cast<const float4*>(acb + (size_t)b * ENCD)[ii - 256];
        reinterpret_cast<float4*>(hcs + bb * 1280)[ii] = v;
    }
    __syncthreads();

    int nrows = (162 - ot + 15) >> 4;
    for (int task = wid; task < nrows * 2; task += 16) {
        int r = ot + (task >> 1) * 16;
        int bh = (task & 1) * 8;
        const float* row = (r < 160) ? (fw + (size_t)r * 1280) : (pwm + (size_t)(r - 160) * 1280);
        const float4* r4 = reinterpret_cast<const float4*>(row);
        float4 w[10];
        #pragma unroll
        for (int q = 0; q < 10; q++) w[q] = r4[lane + q * 32];
        #pragma unroll
        for (int bb = 0; bb < 8; bb++) {
            const float4* h4 = reinterpret_cast<const float4*>(hcs + (size_t)(bh + bb) * 1280);
            float sum = 0.f;
            #pragma unroll
            for (int q = 0; q < 10; q++) {
                float4 hv = h4[lane + q * 32];
                sum += w[q].x*hv.x + w[q].y*hv.y + w[q].z*hv.z + w[q].w*hv.w;
            }
            #pragma unroll
            for (int of = 16; of; of >>= 1) sum += __shfl_xor_sync(0xffffffffu, sum, of);
            if (lane == 0) {
                int b = bt * 16 + bh + bb;
                if (r < 160) {
                    int rr = r / NC, ch = r - rr * NC;
                    out[(size_t)b * NC * TFEAT + (size_t)ch * TFEAT + s * 2 + rr] = sum;
                } else {
                    out[LOGIT_OFF + (size_t)b * TFEAT + s * 2 + (r - 160)] = sum + pb[r - 160];
                }
            }
        }
    }
    __syncthreads();
}

// ---------------- persistent decoder (launch #3; 2 barriers/step) --------------
__global__ void __launch_bounds__(THR, 1) k_decoder(
    const float* __restrict__ enc, const int* __restrict__ tlen,
    const float* __restrict__ wdec, const float* __restrict__ watt,
    const float* __restrict__ wattb,
    const float* __restrict__ fow, const float* __restrict__ pow_,
    const float* __restrict__ pob, float* __restrict__ out)
{
    extern __shared__ char sm[];
    float* smf = reinterpret_cast<float*>(sm) + SM_F_OFF;
    uint32_t smb = smem_u32_of(sm);
    int tid = threadIdx.x;
    int blk = blockIdx.x;
    float* attw = out + ATTW_OFF;
    unsigned gen = 0;

    // prologue: attention for step 0 (h0 = 0 in slot 0)
    if (blk < 64)
        att_step(sm, smf, 0, blk, enc, tlen, wdec, watt, wattb, attw, g_h0f);
    gen++; gbar(gen);

    for (int s = 0; s < SSTEPS; s++) {
        int p = s & 1;
        // P1: lstm0 full-K GEMM + pw0 (writes h0 slot p^1)
        lstm_phase<0>(sm, smb, blk, s, p, g_W0h, g_W0l, g_b40,
                      g_h0f + (size_t)p * HSZ, g_h0f + (size_t)(p ^ 1) * HSZ,
                      g_h0h + (size_t)(p ^ 1) * HSZ, g_h0l + (size_t)(p ^ 1) * HSZ,
                      g_c0, tid);
        gen++; gbar(gen);
        // P2: lstm1 + pw1 (writes h1 slot p^1), then att(s+1) / outproj(s-1)
        lstm_phase<1>(sm, smb, blk, s, p, g_W1h, g_W1l, g_b41,
                      g_h1f + (size_t)p * HSZ, g_h1f + (size_t)(p ^ 1) * HSZ,
                      g_h1h + (size_t)(p ^ 1) * HSZ, g_h1l + (size_t)(p ^ 1) * HSZ,
                      g_c1, tid);
        if (blk < 64) {
            if (s + 1 < SSTEPS)
                att_step(sm, smf, s + 1, blk, enc, tlen, wdec, watt, wattb, attw,
                         g_h0f + (size_t)(p ^ 1) * HSZ);
        } else {
            if (s >= 1)
                outproj(smf, s - 1, blk - 64, fow, pow_, pob, out,
                        g_h1f + (size_t)p * HSZ);
        }
        gen++; gbar(gen);
    }
    // tail: outproj for last step; h1(S-1) is in slot ((S-1)&1)^1 = S&1 = 0
    if (blk >= 64)
        outproj(smf, SSTEPS - 1, blk - 64, fow, pow_, pob, out,
                g_h1f + (size_t)(SSTEPS & 1) * HSZ);
}

// ---------------- host ----------------
extern "C" void kernel_launch(void* const* d_in, const int* in_sizes, int n_in,
                              void* d_out, int out_size)
{
    const float* enc    = (const float*)d_in[0];
    const int*   tlen   = (const int*)  d_in[1];
    const float* ft     = (const float*)d_in[2];
    const float* enc_w  = (const float*)d_in[3];
    const float* enc_b  = (const float*)d_in[4];
    const float* dec_w  = (const float*)d_in[5];
    const float* att_w  = (const float*)d_in[6];
    const float* conv_w = (const float*)d_in[7];
    const float* ww     = (const float*)d_in[8];
    const float* wbb    = (const float*)d_in[9];
    const float* pw0    = (const float*)d_in[10];
    const float* pb0    = (const float*)d_in[11];
    const float* pw1    = (const float*)d_in[12];
    const float* pb1    = (const float*)d_in[13];
    const float* l0wih  = (const float*)d_in[14];
    const float* l0whh  = (const float*)d_in[15];
    const float* l0bih  = (const float*)d_in[16];
    const float* l0bhh  = (const float*)d_in[17];
    const float* l1wih  = (const float*)d_in[18];
    const float* l1whh  = (const float*)d_in[19];
    const float* l1bih  = (const float*)d_in[20];
    const float* l1bhh  = (const float*)d_in[21];
    const float* fow    = (const float*)d_in[22];
    const float* pow_   = (const float*)d_in[23];
    const float* pob    = (const float*)d_in[24];
    float* out = (float*)d_out;

    static int smem_set = 0;
    if (!smem_set) {
        cudaFuncSetAttribute(k_decoder, cudaFuncAttributeMaxDynamicSharedMemorySize, SM_TOTAL);
        smem_set = 1;
    }

    // launch indices: 0 setup, 1 gemmA, 2 gemmB, 3 k_decoder (ncu captures #3)
    k_setup<<<2048, 256>>>(att_w, conv_w, l0bih, l0bhh, l1bih, l1bhh,
                           l0wih, l0whh, l1wih, l1whh);
    k_gemmA<<<dim3(700, 4), 256>>>(enc, enc_w, enc_b, ft, pw0, pb0);
    k_gemmB<<<dim3(500, 4), 256>>>(pw1, pb1);
    k_decoder<<<GRID, THR, SM_TOTAL>>>(
        enc, tlen, dec_w, ww, wbb, fow, pow_, pob, out);
}